// round 4
// baseline (speedup 1.0000x reference)
#include <cuda_runtime.h>
#include <math.h>
#include <math_constants.h>
#include <cstdint>

#define BATCH  4
#define SEQ    2048
#define DMODEL 1024
#define NHEADS 16
#define DHEAD  64

// Scratch (device globals — allocation-free per harness rules)
__device__ float g_q[(size_t)BATCH * NHEADS * SEQ * DHEAD];
__device__ float g_k[(size_t)BATCH * NHEADS * SEQ * DHEAD];
__device__ float g_v[(size_t)BATCH * NHEADS * SEQ * DHEAD];
__device__ float g_attn[(size_t)BATCH * SEQ * DMODEL];

// ---------------------------------------------------------------------------
// helpers
// ---------------------------------------------------------------------------
__device__ __forceinline__ float tf32r(float x) {
    float r;
    asm("cvt.rna.tf32.f32 %0, %1;" : "=f"(r) : "f"(x));
    return r;
}

__device__ __forceinline__ uint32_t fbits(float x) { return __float_as_uint(x); }

// Interleave: within a 16-k group, k stored at position ((k&3)<<2)|(k>>2).
// Thread t's LDS.128 at 4t then yields {k=t, t+4, t+8, t+12}.
__device__ __forceinline__ int kperm(int k) {
    return ((k & 3) << 2) | (k >> 2);
}

// D = A(16x8 tf32, row) * B(8x8 tf32, col) + D   (f32 accum)
__device__ __forceinline__ void mma_tf32(float c[4],
                                         uint32_t a0, uint32_t a1,
                                         uint32_t a2, uint32_t a3,
                                         uint32_t b0, uint32_t b1) {
    asm volatile(
        "mma.sync.aligned.m16n8k8.row.col.f32.tf32.tf32.f32 "
        "{%0,%1,%2,%3}, {%4,%5,%6,%7}, {%8,%9}, {%0,%1,%2,%3};"
        : "+f"(c[0]), "+f"(c[1]), "+f"(c[2]), "+f"(c[3])
        : "r"(a0), "r"(a1), "r"(a2), "r"(a3), "r"(b0), "r"(b1));
}

// ===========================================================================
// TF32 mma.sync GEMM (NT): C[m,n] = sum_k A[m,k] * W[n,k] + bias[n]
// 128x128x16 block, 256 thr = 8 warps (2m x 4n), warptile 64x32.
// Smem rows hold 16 k-values in kperm order -> LDS.128 fragment loads.
// MODE 0: A = x, scatter into g_q/g_k/g_v ([b,h,s,d]).  MODE 1: A = g_attn.
// ===========================================================================
#define GBK  16
#define BKP  20

template <int MODE>
__global__ __launch_bounds__(256) void gemm_mma(
    const float* __restrict__ A, const float* __restrict__ W,
    const float* __restrict__ bias, float* __restrict__ C,
    int M, int N, int K)
{
    __shared__ float As[2][128 * BKP];
    __shared__ float Bs[2][128 * BKP];

    const int tid  = threadIdx.x;
    const int lane = tid & 31;
    const int g    = lane >> 2;
    const int t    = lane & 3;
    const int wid  = tid >> 5;
    const int wm   = (wid >> 2) * 64;   // 0 / 64
    const int wn   = (wid & 3) * 32;    // 0 / 32 / 64 / 96
    const int bm   = blockIdx.y;
    const int bn   = blockIdx.x;

    const float* Ag = (MODE == 1) ? g_attn : A;
    const int lrow = tid >> 1;          // 0..127
    const int lcol = (tid & 1) * 8;     // 0 / 8
    const float* Ap = Ag + (size_t)(bm * 128 + lrow) * K + lcol;
    const float* Wp = W  + (size_t)(bn * 128 + lrow) * K + lcol;

    float acc[4][4][4];
    #pragma unroll
    for (int mt = 0; mt < 4; mt++)
        #pragma unroll
        for (int nt = 0; nt < 4; nt++)
            #pragma unroll
            for (int e = 0; e < 4; e++) acc[mt][nt][e] = 0.0f;

    // ---- prologue: stage 0 ----
    {
        float av[8], bv[8];
        *(float4*)(av)     = *(const float4*)(Ap);
        *(float4*)(av + 4) = *(const float4*)(Ap + 4);
        *(float4*)(bv)     = *(const float4*)(Wp);
        *(float4*)(bv + 4) = *(const float4*)(Wp + 4);
        float* as = &As[0][lrow * BKP];
        float* bs = &Bs[0][lrow * BKP];
        #pragma unroll
        for (int j = 0; j < 8; j++) {
            const int pos = kperm(lcol + j);
            as[pos] = tf32r(av[j]);
            bs[pos] = tf32r(bv[j]);
        }
    }
    __syncthreads();

    const int NS = K / GBK;
    for (int s = 0; s < NS; s++) {
        const int buf = s & 1;

        float av[8], bv[8];
        if (s + 1 < NS) {
            const int k0 = (s + 1) * GBK;
            *(float4*)(av)     = *(const float4*)(Ap + k0);
            *(float4*)(av + 4) = *(const float4*)(Ap + k0 + 4);
            *(float4*)(bv)     = *(const float4*)(Wp + k0);
            *(float4*)(bv + 4) = *(const float4*)(Wp + k0 + 4);
        }

        // ---- fragments + mma (covers both k8 chunks in one pass) ----
        float4 fb[4];
        #pragma unroll
        for (int nt = 0; nt < 4; nt++)
            fb[nt] = *(const float4*)&Bs[buf][(wn + nt * 8 + g) * BKP + 4 * t];

        #pragma unroll
        for (int mt = 0; mt < 4; mt++) {
            const float4 f0 = *(const float4*)&As[buf][(wm + mt * 16 + g) * BKP + 4 * t];
            const float4 f1 = *(const float4*)&As[buf][(wm + mt * 16 + g + 8) * BKP + 4 * t];
            #pragma unroll
            for (int nt = 0; nt < 4; nt++) {
                mma_tf32(acc[mt][nt], fbits(f0.x), fbits(f1.x), fbits(f0.y), fbits(f1.y),
                         fbits(fb[nt].x), fbits(fb[nt].y));
                mma_tf32(acc[mt][nt], fbits(f0.z), fbits(f1.z), fbits(f0.w), fbits(f1.w),
                         fbits(fb[nt].z), fbits(fb[nt].w));
            }
        }

        if (s + 1 < NS) {
            float* as = &As[buf ^ 1][lrow * BKP];
            float* bs = &Bs[buf ^ 1][lrow * BKP];
            #pragma unroll
            for (int j = 0; j < 8; j++) {
                const int pos = kperm(lcol + j);
                as[pos] = tf32r(av[j]);
                bs[pos] = tf32r(bv[j]);
            }
        }
        __syncthreads();
    }

    // ---- epilogue ----
    #pragma unroll
    for (int mt = 0; mt < 4; mt++) {
        #pragma unroll
        for (int half = 0; half < 2; half++) {        // rows g / g+8
            const int m = bm * 128 + wm + mt * 16 + g + half * 8;
            const int bb_ = m >> 11;
            const int srow = m & 2047;
            #pragma unroll
            for (int nt = 0; nt < 4; nt++) {
                const int n = bn * 128 + wn + nt * 8 + 2 * t;
                float2 bvv = *(const float2*)(bias + n);
                float2 v;
                v.x = acc[mt][nt][half * 2 + 0] + bvv.x;
                v.y = acc[mt][nt][half * 2 + 1] + bvv.y;
                if (MODE == 0) {
                    const int part = n >> 10;
                    const int hd = n & 1023;
                    const int hh = hd >> 6;
                    const int d = hd & 63;
                    float* dst = (part == 0) ? g_q : (part == 1) ? g_k : g_v;
                    *(float2*)(dst + (((size_t)(bb_ * NHEADS + hh)) * SEQ + srow) * DHEAD + d) = v;
                } else {
                    *(float2*)(C + (size_t)m * N + n) = v;
                }
            }
        }
    }
}

// ===========================================================================
// Flash attention on mma.sync TF32 with LDS.128 fragment loads.
// CTA = (b, h, 64-row q-tile), 128 thr = 4 warps, warp owns 16 q-rows.
// Ks[key][d] (d kperm-interleaved), Vt[d][key] (key kperm-interleaved),
// Ps[q][d-or-key] (interleaved).  All strides 80 (conflict-free phases).
// ===========================================================================
#define FSTR 80
#define FLASH_SMEM (3 * 64 * FSTR * 4)

__global__ __launch_bounds__(128) void flash_mma(const int* __restrict__ maskFlag)
{
    extern __shared__ float smf[];
    float* Ks = smf;                 // [64 keys][FSTR]
    float* Vt = smf + 64 * FSTR;     // [64 d][FSTR]   (V transposed)
    float* Ps = Vt + 64 * FSTR;      // [64 q][FSTR]   (Q then P)

    const int tid  = threadIdx.x;
    const int lane = tid & 31;
    const int w    = tid >> 5;
    const int g    = lane >> 2;
    const int t    = lane & 3;
    const int qt   = (int)gridDim.x - 1 - (int)blockIdx.x;  // heavy tiles first
    const int h    = blockIdx.y;
    const int b    = blockIdx.z;
    const int causal = maskFlag[0];

    const size_t bh = (size_t)(b * NHEADS + h) * SEQ * DHEAD;
    const float* Qg = g_q + bh + (size_t)qt * 64 * DHEAD;
    const float* Kg = g_k + bh;
    const float* Vg = g_v + bh;

    // ---- stage Q (scaled, tf32-rounded, kperm-interleaved) into Ps ----
    for (int i = tid; i < 64 * 16; i += 128) {
        const int r  = i >> 4;
        const int c4 = (i & 15) * 4;
        float4 v = *(const float4*)(Qg + r * 64 + c4);
        float* p = &Ps[r * FSTR + (c4 & ~15) + ((c4 & 15) >> 2)];
        p[0]  = tf32r(v.x * 0.125f);
        p[4]  = tf32r(v.y * 0.125f);
        p[8]  = tf32r(v.z * 0.125f);
        p[12] = tf32r(v.w * 0.125f);
    }
    __syncthreads();

    // Q fragments: qf[kg][0..3]=kk even chunk, [4..7]=kk odd chunk
    uint32_t qf[4][8];
    #pragma unroll
    for (int kg = 0; kg < 4; kg++) {
        float4 f0 = *(const float4*)&Ps[(w * 16 + g)     * FSTR + kg * 16 + 4 * t];
        float4 f1 = *(const float4*)&Ps[(w * 16 + g + 8) * FSTR + kg * 16 + 4 * t];
        qf[kg][0] = fbits(f0.x); qf[kg][1] = fbits(f1.x);
        qf[kg][2] = fbits(f0.y); qf[kg][3] = fbits(f1.y);
        qf[kg][4] = fbits(f0.z); qf[kg][5] = fbits(f1.z);
        qf[kg][6] = fbits(f0.w); qf[kg][7] = fbits(f1.w);
    }

    float of[8][4];
    #pragma unroll
    for (int nt = 0; nt < 8; nt++)
        #pragma unroll
        for (int e = 0; e < 4; e++) of[nt][e] = 0.0f;

    float mA = -CUDART_INF_F, mB = -CUDART_INF_F;
    float lA = 0.0f, lB = 0.0f;

    const int ktEnd = causal ? qt : (SEQ / 64 - 1);

    for (int kt = 0; kt <= ktEnd; kt++) {
        __syncthreads();   // previous iteration done with Ks/Vt
        const float* Kt = Kg + (size_t)kt * 64 * DHEAD;
        const float* Vp = Vg + (size_t)kt * 64 * DHEAD;
        for (int i = tid; i < 64 * 16; i += 128) {
            const int r  = i >> 4;          // key index
            const int c4 = (i & 15) * 4;    // d base
            float4 kv = *(const float4*)(Kt + r * 64 + c4);
            float* kp = &Ks[r * FSTR + (c4 & ~15) + ((c4 & 15) >> 2)];
            kp[0]  = tf32r(kv.x);
            kp[4]  = tf32r(kv.y);
            kp[8]  = tf32r(kv.z);
            kp[12] = tf32r(kv.w);
            // V transposed: Vt[d][keypos]
            float4 vv = *(const float4*)(Vp + r * 64 + c4);
            const int kpos = (r & ~15) + kperm(r & 15);
            Vt[(c4 + 0) * FSTR + kpos] = tf32r(vv.x);
            Vt[(c4 + 1) * FSTR + kpos] = tf32r(vv.y);
            Vt[(c4 + 2) * FSTR + kpos] = tf32r(vv.z);
            Vt[(c4 + 3) * FSTR + kpos] = tf32r(vv.w);
        }
        __syncthreads();

        // ---- S = (Q/8) K^T : m16 x n64, k=64 ----
        float sf[8][4];
        #pragma unroll
        for (int nt = 0; nt < 8; nt++)
            #pragma unroll
            for (int e = 0; e < 4; e++) sf[nt][e] = 0.0f;

        #pragma unroll
        for (int kg = 0; kg < 4; kg++) {
            #pragma unroll
            for (int nt = 0; nt < 8; nt++) {
                float4 fbk = *(const float4*)&Ks[(nt * 8 + g) * FSTR + kg * 16 + 4 * t];
                mma_tf32(sf[nt], qf[kg][0], qf[kg][1], qf[kg][2], qf[kg][3],
                         fbits(fbk.x), fbits(fbk.y));
                mma_tf32(sf[nt], qf[kg][4], qf[kg][5], qf[kg][6], qf[kg][7],
                         fbits(fbk.z), fbits(fbk.w));
            }
        }

        // ---- causal mask on the diagonal tile ----
        if (causal && kt == qt) {
            #pragma unroll
            for (int nt = 0; nt < 8; nt++) {
                #pragma unroll
                for (int e = 0; e < 4; e++) {
                    const int col = nt * 8 + 2 * t + (e & 1);
                    const int row = w * 16 + g + ((e >> 1) << 3);
                    if (col > row) sf[nt][e] = -CUDART_INF_F;
                }
            }
        }

        // ---- online softmax (rows: A = g, B = g+8) ----
        float mxA = -CUDART_INF_F, mxB = -CUDART_INF_F;
        #pragma unroll
        for (int nt = 0; nt < 8; nt++) {
            mxA = fmaxf(mxA, fmaxf(sf[nt][0], sf[nt][1]));
            mxB = fmaxf(mxB, fmaxf(sf[nt][2], sf[nt][3]));
        }
        mxA = fmaxf(mxA, __shfl_xor_sync(0xffffffffu, mxA, 1));
        mxA = fmaxf(mxA, __shfl_xor_sync(0xffffffffu, mxA, 2));
        mxB = fmaxf(mxB, __shfl_xor_sync(0xffffffffu, mxB, 1));
        mxB = fmaxf(mxB, __shfl_xor_sync(0xffffffffu, mxB, 2));

        const float mnA = fmaxf(mA, mxA);
        const float mnB = fmaxf(mB, mxB);
        const float aA = __expf(mA - mnA);
        const float aB = __expf(mB - mnB);
        float sA = 0.0f, sB = 0.0f;
        #pragma unroll
        for (int nt = 0; nt < 8; nt++) {
            sf[nt][0] = __expf(sf[nt][0] - mnA);
            sf[nt][1] = __expf(sf[nt][1] - mnA);
            sf[nt][2] = __expf(sf[nt][2] - mnB);
            sf[nt][3] = __expf(sf[nt][3] - mnB);
            sA += sf[nt][0] + sf[nt][1];
            sB += sf[nt][2] + sf[nt][3];
        }
        sA += __shfl_xor_sync(0xffffffffu, sA, 1);
        sA += __shfl_xor_sync(0xffffffffu, sA, 2);
        sB += __shfl_xor_sync(0xffffffffu, sB, 1);
        sB += __shfl_xor_sync(0xffffffffu, sB, 2);
        lA = lA * aA + sA;
        lB = lB * aB + sB;
        mA = mnA;
        mB = mnB;
        #pragma unroll
        for (int nt = 0; nt < 8; nt++) {
            of[nt][0] *= aA; of[nt][1] *= aA;
            of[nt][2] *= aB; of[nt][3] *= aB;
        }

        // ---- write P (per-warp-private rows, kperm-interleaved cols) ----
        #pragma unroll
        for (int nt = 0; nt < 8; nt++) {
            const int c0 = nt * 8 + 2 * t;
            const int p0 = (c0 & ~15) + kperm(c0 & 15);
            const int p1 = ((c0 + 1) & ~15) + kperm((c0 + 1) & 15);
            float* r0 = &Ps[(w * 16 + g) * FSTR];
            float* r1 = &Ps[(w * 16 + g + 8) * FSTR];
            r0[p0] = tf32r(sf[nt][0]); r0[p1] = tf32r(sf[nt][1]);
            r1[p0] = tf32r(sf[nt][2]); r1[p1] = tf32r(sf[nt][3]);
        }
        __syncwarp();

        // ---- O += P V : m16 x n64, k=64 ----
        #pragma unroll
        for (int kg = 0; kg < 4; kg++) {
            float4 p0 = *(const float4*)&Ps[(w * 16 + g)     * FSTR + kg * 16 + 4 * t];
            float4 p1 = *(const float4*)&Ps[(w * 16 + g + 8) * FSTR + kg * 16 + 4 * t];
            #pragma unroll
            for (int nt = 0; nt < 8; nt++) {
                float4 fv = *(const float4*)&Vt[(nt * 8 + g) * FSTR + kg * 16 + 4 * t];
                mma_tf32(of[nt], fbits(p0.x), fbits(p1.x), fbits(p0.y), fbits(p1.y),
                         fbits(fv.x), fbits(fv.y));
                mma_tf32(of[nt], fbits(p0.z), fbits(p1.z), fbits(p0.w), fbits(p1.w),
                         fbits(fv.z), fbits(fv.w));
            }
        }
    }

    // ---- epilogue: normalize, store to g_attn [b, s, h*64+d] ----
    const float iA = 1.0f / lA;
    const float iB = 1.0f / lB;
    const int qrow = qt * 64 + w * 16;
    #pragma unroll
    for (int nt = 0; nt < 8; nt++) {
        const int d = h * 64 + nt * 8 + 2 * t;
        float2 v0, v1;
        v0.x = of[nt][0] * iA; v0.y = of[nt][1] * iA;
        v1.x = of[nt][2] * iB; v1.y = of[nt][3] * iB;
        *(float2*)(g_attn + ((size_t)b * SEQ + qrow + g) * DMODEL + d) = v0;
        *(float2*)(g_attn + ((size_t)b * SEQ + qrow + g + 8) * DMODEL + d) = v1;
    }
}

// ---------------------------------------------------------------------------
extern "C" void kernel_launch(void* const* d_in, const int* in_sizes, int n_in,
                              void* d_out, int out_size)
{
    const float* x   = (const float*)d_in[0];   // [4, 2048, 1024]
    const float* w1  = (const float*)d_in[1];   // [3072, 1024]
    const float* b1  = (const float*)d_in[2];   // [3072]
    const float* w2  = (const float*)d_in[3];   // [1024, 1024]
    const float* b2  = (const float*)d_in[4];   // [1024]
    const int*   msk = (const int*)  d_in[5];   // causal flag
    float* out = (float*)d_out;

    const int M = BATCH * SEQ;   // 8192

    // 1) QKV projection (mma.sync tf32) -> g_q/g_k/g_v
    gemm_mma<0><<<dim3(3 * DMODEL / 128, M / 128), 256>>>(
        x, w1, b1, nullptr, M, 3 * DMODEL, DMODEL);

    // 2) Flash attention (mma.sync tf32) -> g_attn
    cudaFuncSetAttribute(flash_mma,
                         cudaFuncAttributeMaxDynamicSharedMemorySize, FLASH_SMEM);
    flash_mma<<<dim3(SEQ / 64, NHEADS, BATCH), 128, FLASH_SMEM>>>(msk);

    // 3) Output projection (mma.sync tf32) -> d_out
    gemm_mma<1><<<dim3(DMODEL / 128, M / 128), 256>>>(
        nullptr, w2, b2, out, M, DMODEL, DMODEL);
}

// round 5
// speedup vs baseline: 1.2527x; 1.2527x over previous
#include <cuda_runtime.h>
#include <math.h>
#include <math_constants.h>
#include <cstdint>

#define BATCH  4
#define SEQ    2048
#define DMODEL 1024
#define NHEADS 16
#define DHEAD  64

// Scratch (device globals — allocation-free per harness rules)
__device__ float g_q[(size_t)BATCH * NHEADS * SEQ * DHEAD];
__device__ float g_k[(size_t)BATCH * NHEADS * SEQ * DHEAD];
__device__ float g_v[(size_t)BATCH * NHEADS * SEQ * DHEAD];
__device__ float g_attn[(size_t)BATCH * SEQ * DMODEL];

// ---------------------------------------------------------------------------
// helpers
// ---------------------------------------------------------------------------
__device__ __forceinline__ float tf32r(float x) {
    float r;
    asm("cvt.rna.tf32.f32 %0, %1;" : "=f"(r) : "f"(x));
    return r;
}

__device__ __forceinline__ uint32_t fbits(float x) { return __float_as_uint(x); }

// D = A(16x8 tf32, row) * B(8x8 tf32, col) + D   (f32 accum)
__device__ __forceinline__ void mma_tf32(float c[4],
                                         uint32_t a0, uint32_t a1,
                                         uint32_t a2, uint32_t a3,
                                         uint32_t b0, uint32_t b1) {
    asm volatile(
        "mma.sync.aligned.m16n8k8.row.col.f32.tf32.tf32.f32 "
        "{%0,%1,%2,%3}, {%4,%5,%6,%7}, {%8,%9}, {%0,%1,%2,%3};"
        : "+f"(c[0]), "+f"(c[1]), "+f"(c[2]), "+f"(c[3])
        : "r"(a0), "r"(a1), "r"(a2), "r"(a3), "r"(b0), "r"(b1));
}

// ===========================================================================
// TF32 mma.sync GEMM (NT): C[m,n] = sum_k A[m,k] * W[n,k] + bias[n]
// 128x256x16 CTA tile, 256 thr = 8 warps (2m x 4n), warptile 64x64.
// R3-style smem layout: BKP=20 pad, contiguous tf32r staging stores,
// conflict-free scalar fragment loads.
// MODE 0: A = x, scatter into g_q/g_k/g_v ([b,h,s,d]).  MODE 1: A = g_attn.
// ===========================================================================
#define GBK  16
#define BKP  20
#define GBM  128
#define GBN  256
#define GEMM_SMEM ((2 * GBM * BKP + 2 * GBN * BKP) * 4)   // 61440

template <int MODE>
__global__ __launch_bounds__(256) void gemm_mma(
    const float* __restrict__ A, const float* __restrict__ W,
    const float* __restrict__ bias, float* __restrict__ C,
    int M, int N, int K)
{
    extern __shared__ float smg[];
    float* As = smg;                       // [2][GBM*BKP]
    float* Bs = smg + 2 * GBM * BKP;       // [2][GBN*BKP]

    const int tid  = threadIdx.x;
    const int lane = tid & 31;
    const int g    = lane >> 2;
    const int t    = lane & 3;
    const int wid  = tid >> 5;
    const int wm   = (wid >> 2) * 64;   // 0 / 64
    const int wn   = (wid & 3) * 64;    // 0 / 64 / 128 / 192
    const int bm   = blockIdx.y;
    const int bn   = blockIdx.x;

    const float* Ag = (MODE == 1) ? g_attn : A;
    const int lrowA = tid >> 1;          // 0..127
    const int lcolA = (tid & 1) * 8;     // 0 / 8
    const float* Ap = Ag + (size_t)(bm * GBM + lrowA) * K + lcolA;
    const float* Wp = W  + (size_t)(bn * GBN + tid) * K;   // 1 row / thread

    float acc[4][8][4];
    #pragma unroll
    for (int mt = 0; mt < 4; mt++)
        #pragma unroll
        for (int nt = 0; nt < 8; nt++)
            #pragma unroll
            for (int e = 0; e < 4; e++) acc[mt][nt][e] = 0.0f;

    // ---- prologue: stage 0 ----
    {
        float av[8], bv[16];
        *(float4*)(av)     = *(const float4*)(Ap);
        *(float4*)(av + 4) = *(const float4*)(Ap + 4);
        *(float4*)(bv)      = *(const float4*)(Wp);
        *(float4*)(bv + 4)  = *(const float4*)(Wp + 4);
        *(float4*)(bv + 8)  = *(const float4*)(Wp + 8);
        *(float4*)(bv + 12) = *(const float4*)(Wp + 12);
        float* as = &As[lrowA * BKP + lcolA];
        float* bs = &Bs[tid * BKP];
        #pragma unroll
        for (int j = 0; j < 8; j++) as[j] = tf32r(av[j]);
        #pragma unroll
        for (int j = 0; j < 16; j++) bs[j] = tf32r(bv[j]);
    }
    __syncthreads();

    const int NS = K / GBK;
    for (int s = 0; s < NS; s++) {
        const int buf = s & 1;
        const float* Asb = As + buf * GBM * BKP;
        const float* Bsb = Bs + buf * GBN * BKP;

        float av[8], bv[16];
        if (s + 1 < NS) {
            const int k0 = (s + 1) * GBK;
            *(float4*)(av)     = *(const float4*)(Ap + k0);
            *(float4*)(av + 4) = *(const float4*)(Ap + k0 + 4);
            *(float4*)(bv)      = *(const float4*)(Wp + k0);
            *(float4*)(bv + 4)  = *(const float4*)(Wp + k0 + 4);
            *(float4*)(bv + 8)  = *(const float4*)(Wp + k0 + 8);
            *(float4*)(bv + 12) = *(const float4*)(Wp + k0 + 12);
        }

        #pragma unroll
        for (int kk = 0; kk < 2; kk++) {
            uint32_t af[4][4];
            #pragma unroll
            for (int mt = 0; mt < 4; mt++) {
                const float* base = &Asb[(wm + mt * 16) * BKP + kk * 8];
                af[mt][0] = fbits(base[g * BKP + t]);
                af[mt][1] = fbits(base[(g + 8) * BKP + t]);
                af[mt][2] = fbits(base[g * BKP + t + 4]);
                af[mt][3] = fbits(base[(g + 8) * BKP + t + 4]);
            }
            #pragma unroll
            for (int nt = 0; nt < 8; nt++) {
                const float* bb = &Bsb[(wn + nt * 8 + g) * BKP + kk * 8];
                const uint32_t b0 = fbits(bb[t]);
                const uint32_t b1 = fbits(bb[t + 4]);
                #pragma unroll
                for (int mt = 0; mt < 4; mt++)
                    mma_tf32(acc[mt][nt], af[mt][0], af[mt][1], af[mt][2], af[mt][3],
                             b0, b1);
            }
        }

        if (s + 1 < NS) {
            float* as = &As[(buf ^ 1) * GBM * BKP + lrowA * BKP + lcolA];
            float* bs = &Bs[(buf ^ 1) * GBN * BKP + tid * BKP];
            #pragma unroll
            for (int j = 0; j < 8; j++) as[j] = tf32r(av[j]);
            #pragma unroll
            for (int j = 0; j < 16; j++) bs[j] = tf32r(bv[j]);
        }
        __syncthreads();
    }

    // ---- epilogue ----
    #pragma unroll
    for (int mt = 0; mt < 4; mt++) {
        #pragma unroll
        for (int half = 0; half < 2; half++) {        // rows g / g+8
            const int m = bm * GBM + wm + mt * 16 + g + half * 8;
            const int bb_ = m >> 11;
            const int srow = m & 2047;
            #pragma unroll
            for (int nt = 0; nt < 8; nt++) {
                const int n = bn * GBN + wn + nt * 8 + 2 * t;
                float2 bvv = *(const float2*)(bias + n);
                float2 v;
                v.x = acc[mt][nt][half * 2 + 0] + bvv.x;
                v.y = acc[mt][nt][half * 2 + 1] + bvv.y;
                if (MODE == 0) {
                    const int part = n >> 10;
                    const int hd = n & 1023;
                    const int hh = hd >> 6;
                    const int d = hd & 63;
                    float* dst = (part == 0) ? g_q : (part == 1) ? g_k : g_v;
                    *(float2*)(dst + (((size_t)(bb_ * NHEADS + hh)) * SEQ + srow) * DHEAD + d) = v;
                } else {
                    *(float2*)(C + (size_t)m * N + n) = v;
                }
            }
        }
    }
}

// ===========================================================================
// Flash attention on mma.sync TF32 (R3 layout, 128-row q-tile).
// CTA = (b, h, 128-row q-tile), 128 thr = 4 warps, warp owns 32 q-rows
// (two m16 row-blocks). K tile = 64 keys.
// Q pre-scaled by 0.125*log2(e); softmax in base-2 (exp2f).
// Ks[64][68], Vs[64][72] (row-major, read as col-major B), Ps[128][68].
// ===========================================================================
#define KSTR 68
#define VSTR 72
#define QTILE 128
#define FLASH_SMEM ((64 * KSTR + 64 * VSTR + QTILE * KSTR) * 4)   // 70656

__global__ __launch_bounds__(128) void flash_mma(const int* __restrict__ maskFlag)
{
    extern __shared__ float smf[];
    float* Ks = smf;                 // [64 keys][KSTR]
    float* Vs = smf + 64 * KSTR;     // [64 keys][VSTR]
    float* Ps = Vs + 64 * VSTR;      // [128 q][KSTR]  (Q then P)

    const int tid  = threadIdx.x;
    const int lane = tid & 31;
    const int w    = tid >> 5;
    const int g    = lane >> 2;
    const int t    = lane & 3;
    const int qt   = (int)gridDim.x - 1 - (int)blockIdx.x;  // heavy tiles first
    const int h    = blockIdx.y;
    const int b    = blockIdx.z;
    const int causal = maskFlag[0];

    const size_t bh = (size_t)(b * NHEADS + h) * SEQ * DHEAD;
    const float* Qg = g_q + bh + (size_t)qt * QTILE * DHEAD;
    const float* Kg = g_k + bh;
    const float* Vg = g_v + bh;

    const float SCALE = 0.125f * 1.4426950408889634f;   // (1/sqrt(64))*log2(e)

    // ---- stage Q (scaled, tf32-rounded) into Ps ----
    for (int i = tid; i < QTILE * 16; i += 128) {
        const int r  = i >> 4;
        const int c4 = (i & 15) * 4;
        float4 v = *(const float4*)(Qg + r * 64 + c4);
        float* p = &Ps[r * KSTR + c4];
        p[0] = tf32r(v.x * SCALE);
        p[1] = tf32r(v.y * SCALE);
        p[2] = tf32r(v.z * SCALE);
        p[3] = tf32r(v.w * SCALE);
    }
    __syncthreads();

    // Q fragments for both row-blocks
    uint32_t qf[2][8][4];
    #pragma unroll
    for (int r = 0; r < 2; r++) {
        #pragma unroll
        for (int k8 = 0; k8 < 8; k8++) {
            const float* base = &Ps[(w * 32 + r * 16) * KSTR + k8 * 8];
            qf[r][k8][0] = fbits(base[g * KSTR + t]);
            qf[r][k8][1] = fbits(base[(g + 8) * KSTR + t]);
            qf[r][k8][2] = fbits(base[g * KSTR + t + 4]);
            qf[r][k8][3] = fbits(base[(g + 8) * KSTR + t + 4]);
        }
    }

    float of[2][8][4];
    float mrun[2][2], lrun[2][2];
    #pragma unroll
    for (int r = 0; r < 2; r++) {
        mrun[r][0] = mrun[r][1] = -CUDART_INF_F;
        lrun[r][0] = lrun[r][1] = 0.0f;
        #pragma unroll
        for (int nt = 0; nt < 8; nt++)
            #pragma unroll
            for (int e = 0; e < 4; e++) of[r][nt][e] = 0.0f;
    }

    const int ktEnd = causal ? (2 * qt + 1) : (SEQ / 64 - 1);

    for (int kt = 0; kt <= ktEnd; kt++) {
        __syncthreads();   // previous iteration done with Ks/Vs/Ps
        const float* Kt = Kg + (size_t)kt * 64 * DHEAD;
        const float* Vp = Vg + (size_t)kt * 64 * DHEAD;
        for (int i = tid; i < 64 * 16; i += 128) {
            const int r  = i >> 4;
            const int c4 = (i & 15) * 4;
            float4 kv = *(const float4*)(Kt + r * 64 + c4);
            float* kp = &Ks[r * KSTR + c4];
            kp[0] = tf32r(kv.x); kp[1] = tf32r(kv.y);
            kp[2] = tf32r(kv.z); kp[3] = tf32r(kv.w);
            float4 vv = *(const float4*)(Vp + r * 64 + c4);
            float* vp = &Vs[r * VSTR + c4];
            vp[0] = tf32r(vv.x); vp[1] = tf32r(vv.y);
            vp[2] = tf32r(vv.z); vp[3] = tf32r(vv.w);
        }
        __syncthreads();

        const bool diag = causal && (kt >= 2 * qt);

        #pragma unroll
        for (int r = 0; r < 2; r++) {
            // ---- S2 = (Q*scale*log2e) K^T : m16 x n64, k=64 ----
            float sf[8][4];
            #pragma unroll
            for (int nt = 0; nt < 8; nt++)
                #pragma unroll
                for (int e = 0; e < 4; e++) sf[nt][e] = 0.0f;

            #pragma unroll
            for (int k8 = 0; k8 < 8; k8++) {
                #pragma unroll
                for (int nt = 0; nt < 8; nt++) {
                    const float* bb = &Ks[(nt * 8 + g) * KSTR + k8 * 8];
                    mma_tf32(sf[nt], qf[r][k8][0], qf[r][k8][1],
                             qf[r][k8][2], qf[r][k8][3],
                             fbits(bb[t]), fbits(bb[t + 4]));
                }
            }

            // ---- causal mask ----
            if (diag) {
                const int rowb = qt * QTILE + w * 32 + r * 16;
                const int colb = kt * 64;
                #pragma unroll
                for (int nt = 0; nt < 8; nt++) {
                    #pragma unroll
                    for (int e = 0; e < 4; e++) {
                        const int col = colb + nt * 8 + 2 * t + (e & 1);
                        const int row = rowb + g + ((e >> 1) << 3);
                        if (col > row) sf[nt][e] = -CUDART_INF_F;
                    }
                }
            }

            // ---- online softmax in base 2 (rows: A = g, B = g+8) ----
            float mxA = -CUDART_INF_F, mxB = -CUDART_INF_F;
            #pragma unroll
            for (int nt = 0; nt < 8; nt++) {
                mxA = fmaxf(mxA, fmaxf(sf[nt][0], sf[nt][1]));
                mxB = fmaxf(mxB, fmaxf(sf[nt][2], sf[nt][3]));
            }
            mxA = fmaxf(mxA, __shfl_xor_sync(0xffffffffu, mxA, 1));
            mxA = fmaxf(mxA, __shfl_xor_sync(0xffffffffu, mxA, 2));
            mxB = fmaxf(mxB, __shfl_xor_sync(0xffffffffu, mxB, 1));
            mxB = fmaxf(mxB, __shfl_xor_sync(0xffffffffu, mxB, 2));

            const float mnA = fmaxf(mrun[r][0], mxA);
            const float mnB = fmaxf(mrun[r][1], mxB);
            const float aA = exp2f(mrun[r][0] - mnA);
            const float aB = exp2f(mrun[r][1] - mnB);
            float sA = 0.0f, sB = 0.0f;
            #pragma unroll
            for (int nt = 0; nt < 8; nt++) {
                sf[nt][0] = exp2f(sf[nt][0] - mnA);
                sf[nt][1] = exp2f(sf[nt][1] - mnA);
                sf[nt][2] = exp2f(sf[nt][2] - mnB);
                sf[nt][3] = exp2f(sf[nt][3] - mnB);
                sA += sf[nt][0] + sf[nt][1];
                sB += sf[nt][2] + sf[nt][3];
            }
            sA += __shfl_xor_sync(0xffffffffu, sA, 1);
            sA += __shfl_xor_sync(0xffffffffu, sA, 2);
            sB += __shfl_xor_sync(0xffffffffu, sB, 1);
            sB += __shfl_xor_sync(0xffffffffu, sB, 2);
            lrun[r][0] = lrun[r][0] * aA + sA;
            lrun[r][1] = lrun[r][1] * aB + sB;
            mrun[r][0] = mnA;
            mrun[r][1] = mnB;
            #pragma unroll
            for (int nt = 0; nt < 8; nt++) {
                of[r][nt][0] *= aA; of[r][nt][1] *= aA;
                of[r][nt][2] *= aB; of[r][nt][3] *= aB;
            }

            // ---- write P (warp-private rows) ----
            #pragma unroll
            for (int nt = 0; nt < 8; nt++) {
                const int c = nt * 8 + 2 * t;
                float* p0 = &Ps[(w * 32 + r * 16 + g) * KSTR + c];
                float* p1 = &Ps[(w * 32 + r * 16 + g + 8) * KSTR + c];
                p0[0] = tf32r(sf[nt][0]); p0[1] = tf32r(sf[nt][1]);
                p1[0] = tf32r(sf[nt][2]); p1[1] = tf32r(sf[nt][3]);
            }
        }
        __syncwarp();

        // ---- O += P V : two m16 x n64, k=64 ----
        #pragma unroll
        for (int r = 0; r < 2; r++) {
            #pragma unroll
            for (int k8 = 0; k8 < 8; k8++) {
                const float* base = &Ps[(w * 32 + r * 16) * KSTR + k8 * 8];
                const uint32_t a0 = fbits(base[g * KSTR + t]);
                const uint32_t a1 = fbits(base[(g + 8) * KSTR + t]);
                const uint32_t a2 = fbits(base[g * KSTR + t + 4]);
                const uint32_t a3 = fbits(base[(g + 8) * KSTR + t + 4]);
                #pragma unroll
                for (int nt = 0; nt < 8; nt++) {
                    const uint32_t b0 = fbits(Vs[(k8 * 8 + t) * VSTR + nt * 8 + g]);
                    const uint32_t b1 = fbits(Vs[(k8 * 8 + t + 4) * VSTR + nt * 8 + g]);
                    mma_tf32(of[r][nt], a0, a1, a2, a3, b0, b1);
                }
            }
        }
    }

    // ---- epilogue: normalize, store to g_attn [b, s, h*64+d] ----
    #pragma unroll
    for (int r = 0; r < 2; r++) {
        const float iA = 1.0f / lrun[r][0];
        const float iB = 1.0f / lrun[r][1];
        const int qrow = qt * QTILE + w * 32 + r * 16;
        #pragma unroll
        for (int nt = 0; nt < 8; nt++) {
            const int d = h * 64 + nt * 8 + 2 * t;
            float2 v0, v1;
            v0.x = of[r][nt][0] * iA; v0.y = of[r][nt][1] * iA;
            v1.x = of[r][nt][2] * iB; v1.y = of[r][nt][3] * iB;
            *(float2*)(g_attn + ((size_t)b * SEQ + qrow + g) * DMODEL + d) = v0;
            *(float2*)(g_attn + ((size_t)b * SEQ + qrow + g + 8) * DMODEL + d) = v1;
        }
    }
}

// ---------------------------------------------------------------------------
extern "C" void kernel_launch(void* const* d_in, const int* in_sizes, int n_in,
                              void* d_out, int out_size)
{
    const float* x   = (const float*)d_in[0];   // [4, 2048, 1024]
    const float* w1  = (const float*)d_in[1];   // [3072, 1024]
    const float* b1  = (const float*)d_in[2];   // [3072]
    const float* w2  = (const float*)d_in[3];   // [1024, 1024]
    const float* b2  = (const float*)d_in[4];   // [1024]
    const int*   msk = (const int*)  d_in[5];   // causal flag
    float* out = (float*)d_out;

    const int M = BATCH * SEQ;   // 8192

    cudaFuncSetAttribute(gemm_mma<0>,
                         cudaFuncAttributeMaxDynamicSharedMemorySize, GEMM_SMEM);
    cudaFuncSetAttribute(gemm_mma<1>,
                         cudaFuncAttributeMaxDynamicSharedMemorySize, GEMM_SMEM);
    cudaFuncSetAttribute(flash_mma,
                         cudaFuncAttributeMaxDynamicSharedMemorySize, FLASH_SMEM);

    // 1) QKV projection (mma.sync tf32) -> g_q/g_k/g_v
    gemm_mma<0><<<dim3(3 * DMODEL / GBN, M / GBM), 256, GEMM_SMEM>>>(
        x, w1, b1, nullptr, M, 3 * DMODEL, DMODEL);

    // 2) Flash attention (mma.sync tf32) -> g_attn
    flash_mma<<<dim3(SEQ / QTILE, NHEADS, BATCH), 128, FLASH_SMEM>>>(msk);

    // 3) Output projection (mma.sync tf32) -> d_out
    gemm_mma<1><<<dim3(DMODEL / GBN, M / GBM), 256, GEMM_SMEM>>>(
        nullptr, w2, b2, out, M, DMODEL, DMODEL);
}

// round 7
// speedup vs baseline: 1.4649x; 1.1694x over previous
#include <cuda_runtime.h>
#include <math.h>
#include <math_constants.h>
#include <cstdint>

#define BATCH  4
#define SEQ    2048
#define DMODEL 1024
#define NHEADS 16
#define DHEAD  64

// Scratch (device globals — allocation-free per harness rules)
__device__ float g_q[(size_t)BATCH * NHEADS * SEQ * DHEAD];
__device__ float g_k[(size_t)BATCH * NHEADS * SEQ * DHEAD];
__device__ float g_v[(size_t)BATCH * NHEADS * SEQ * DHEAD];
__device__ float g_attn[(size_t)BATCH * SEQ * DMODEL];

// ---------------------------------------------------------------------------
// helpers
// ---------------------------------------------------------------------------
__device__ __forceinline__ float tf32r(float x) {
    float r;
    asm("cvt.rna.tf32.f32 %0, %1;" : "=f"(r) : "f"(x));
    return r;
}

__device__ __forceinline__ uint32_t fbits(float x) { return __float_as_uint(x); }

__device__ __forceinline__ uint32_t smem_u32(const void* p) {
    uint32_t a;
    asm("{ .reg .u64 t; cvta.to.shared.u64 t, %1; cvt.u32.u64 %0, t; }"
        : "=r"(a) : "l"(p));
    return a;
}

__device__ __forceinline__ void cp16(uint32_t dst, const float* src) {
    asm volatile("cp.async.cg.shared.global [%0], [%1], 16;"
                 :: "r"(dst), "l"(src));
}

#define CP_COMMIT()  asm volatile("cp.async.commit_group;" ::: "memory")
#define CP_WAIT(n)   asm volatile("cp.async.wait_group %0;" :: "n"(n) : "memory")

// D = A(16x8 tf32, row) * B(8x8 tf32, col) + D   (f32 accum)
__device__ __forceinline__ void mma_tf32(float c[4],
                                         uint32_t a0, uint32_t a1,
                                         uint32_t a2, uint32_t a3,
                                         uint32_t b0, uint32_t b1) {
    asm volatile(
        "mma.sync.aligned.m16n8k8.row.col.f32.tf32.tf32.f32 "
        "{%0,%1,%2,%3}, {%4,%5,%6,%7}, {%8,%9}, {%0,%1,%2,%3};"
        : "+f"(c[0]), "+f"(c[1]), "+f"(c[2]), "+f"(c[3])
        : "r"(a0), "r"(a1), "r"(a2), "r"(a3), "r"(b0), "r"(b1));
}

// ===========================================================================
// TF32 mma.sync GEMM (NT): C[m,n] = sum_k A[m,k] * W[n,k] + bias[n]
// 64x128x16 CTA tile, 256 thr = 8 warps (2m x 4n), warptile 32x32.
// 3-stage cp.async pipeline; tf32 RNA conversion at fragment-load time.
// MODE 0: A = x, scatter into g_q/g_k/g_v ([b,h,s,d]).  MODE 1: A = g_attn.
// ===========================================================================
#define GBK  16
#define BKP  20
#define GBM  64
#define GBN  128
#define STG  3

template <int MODE>
__global__ __launch_bounds__(256, 3) void gemm_mma(
    const float* __restrict__ A, const float* __restrict__ W,
    const float* __restrict__ bias, float* __restrict__ C,
    int M, int N, int K)
{
    __shared__ __align__(16) float As[STG][GBM * BKP];
    __shared__ __align__(16) float Bs[STG][GBN * BKP];

    const int tid  = threadIdx.x;
    const int lane = tid & 31;
    const int g    = lane >> 2;
    const int t    = lane & 3;
    const int wid  = tid >> 5;
    const int wm   = (wid >> 2) * 32;   // 0 / 32
    const int wn   = (wid & 3) * 32;    // 0 / 32 / 64 / 96
    const int bm   = blockIdx.y;
    const int bn   = blockIdx.x;

    const float* Ag = (MODE == 1) ? g_attn : A;

    // cp.async source rows/chunks
    const int arow = tid >> 2;            // 0..63
    const int ach  = (tid & 3) * 4;       // 0/4/8/12
    const float* Asrc = Ag + (size_t)(bm * GBM + arow) * K + ach;
    const int brow0 = tid >> 1;           // 0..127
    const int bch0  = (tid & 1) * 8;      // 0 / 8  (thread owns floats bch0..bch0+7)
    const float* Bsrc = W + (size_t)(bn * GBN + brow0) * K + bch0;

    const uint32_t AsBase = smem_u32(&As[0][0]);
    const uint32_t BsBase = smem_u32(&Bs[0][0]);
    const uint32_t aDst = AsBase + (arow * BKP + ach) * 4;
    const uint32_t bDst = BsBase + (brow0 * BKP + bch0) * 4;

    float acc[2][4][4];
    #pragma unroll
    for (int mt = 0; mt < 2; mt++)
        #pragma unroll
        for (int nt = 0; nt < 4; nt++)
            #pragma unroll
            for (int e = 0; e < 4; e++) acc[mt][nt][e] = 0.0f;

    const int NS = K / GBK;

    // ---- prologue: issue stages 0 and 1 ----
    #pragma unroll
    for (int st = 0; st < 2; st++) {
        const int k0 = st * GBK;
        cp16(aDst + st * GBM * BKP * 4, Asrc + k0);
        cp16(bDst + st * GBN * BKP * 4,      Bsrc + k0);
        cp16(bDst + st * GBN * BKP * 4 + 16, Bsrc + k0 + 4);
        CP_COMMIT();
    }

    for (int s = 0; s < NS; s++) {
        const int buf = s % STG;
        if (s == NS - 1) { CP_WAIT(0); } else { CP_WAIT(1); }
        __syncthreads();

        if (s + 2 < NS) {
            const int nbuf = (s + 2) % STG;
            const int k0 = (s + 2) * GBK;
            cp16(aDst + nbuf * GBM * BKP * 4, Asrc + k0);
            cp16(bDst + nbuf * GBN * BKP * 4,      Bsrc + k0);
            cp16(bDst + nbuf * GBN * BKP * 4 + 16, Bsrc + k0 + 4);
            CP_COMMIT();
        }

        const float* Asb = &As[buf][0];
        const float* Bsb = &Bs[buf][0];

        #pragma unroll
        for (int kk = 0; kk < 2; kk++) {
            uint32_t af[2][4];
            #pragma unroll
            for (int mt = 0; mt < 2; mt++) {
                const float* base = &Asb[(wm + mt * 16) * BKP + kk * 8];
                af[mt][0] = fbits(tf32r(base[g * BKP + t]));
                af[mt][1] = fbits(tf32r(base[(g + 8) * BKP + t]));
                af[mt][2] = fbits(tf32r(base[g * BKP + t + 4]));
                af[mt][3] = fbits(tf32r(base[(g + 8) * BKP + t + 4]));
            }
            #pragma unroll
            for (int nt = 0; nt < 4; nt++) {
                const float* bb = &Bsb[(wn + nt * 8 + g) * BKP + kk * 8];
                const uint32_t b0 = fbits(tf32r(bb[t]));
                const uint32_t b1 = fbits(tf32r(bb[t + 4]));
                #pragma unroll
                for (int mt = 0; mt < 2; mt++)
                    mma_tf32(acc[mt][nt], af[mt][0], af[mt][1], af[mt][2], af[mt][3],
                             b0, b1);
            }
        }
        __syncthreads();
    }

    // ---- epilogue ----
    #pragma unroll
    for (int mt = 0; mt < 2; mt++) {
        #pragma unroll
        for (int half = 0; half < 2; half++) {        // rows g / g+8
            const int m = bm * GBM + wm + mt * 16 + g + half * 8;
            const int bb_ = m >> 11;
            const int srow = m & 2047;
            #pragma unroll
            for (int nt = 0; nt < 4; nt++) {
                const int n = bn * GBN + wn + nt * 8 + 2 * t;
                float2 bvv = *(const float2*)(bias + n);
                float2 v;
                v.x = acc[mt][nt][half * 2 + 0] + bvv.x;
                v.y = acc[mt][nt][half * 2 + 1] + bvv.y;
                if (MODE == 0) {
                    const int part = n >> 10;
                    const int hd = n & 1023;
                    const int hh = hd >> 6;
                    const int d = hd & 63;
                    float* dst = (part == 0) ? g_q : (part == 1) ? g_k : g_v;
                    *(float2*)(dst + (((size_t)(bb_ * NHEADS + hh)) * SEQ + srow) * DHEAD + d) = v;
                } else {
                    *(float2*)(C + (size_t)m * N + n) = v;
                }
            }
        }
    }
}

// ===========================================================================
// Flash attention on mma.sync TF32 (128-row q-tile, hoisted fragments).
// CTA = (b, h, 128-row q-tile), 128 thr = 4 warps, warp owns 32 q-rows
// (two m16 row-blocks). K tile = 64 keys. Base-2 softmax.
// Qs[128][68] persistent scaled Q; Ks[64][68]; Vs[64][72]; Ps[128][68].
// ===========================================================================
#define KSTR 68
#define VSTR 72
#define QTILE 128
#define FLASH_SMEM ((64 * KSTR + 64 * VSTR + QTILE * KSTR + QTILE * KSTR) * 4)

__global__ __launch_bounds__(128) void flash_mma(const int* __restrict__ maskFlag)
{
    extern __shared__ float smf[];
    float* Ks = smf;                    // [64 keys][KSTR]
    float* Vs = Ks + 64 * KSTR;         // [64 keys][VSTR]
    float* Qs = Vs + 64 * VSTR;         // [128 q][KSTR]   (persistent)
    float* Ps = Qs + QTILE * KSTR;      // [128 q][KSTR]

    const int tid  = threadIdx.x;
    const int lane = tid & 31;
    const int w    = tid >> 5;
    const int g    = lane >> 2;
    const int t    = lane & 3;
    const int qt   = (int)gridDim.x - 1 - (int)blockIdx.x;  // heavy tiles first
    const int h    = blockIdx.y;
    const int b    = blockIdx.z;
    const int causal = maskFlag[0];

    const size_t bh = (size_t)(b * NHEADS + h) * SEQ * DHEAD;
    const float* Qg = g_q + bh + (size_t)qt * QTILE * DHEAD;
    const float* Kg = g_k + bh;
    const float* Vg = g_v + bh;

    const float SCALE = 0.125f * 1.4426950408889634f;   // (1/sqrt(64))*log2(e)

    // ---- stage Q (scaled, tf32-rounded) into Qs ----
    for (int i = tid; i < QTILE * 16; i += 128) {
        const int r  = i >> 4;
        const int c4 = (i & 15) * 4;
        float4 v = *(const float4*)(Qg + r * 64 + c4);
        float* p = &Qs[r * KSTR + c4];
        p[0] = tf32r(v.x * SCALE);
        p[1] = tf32r(v.y * SCALE);
        p[2] = tf32r(v.z * SCALE);
        p[3] = tf32r(v.w * SCALE);
    }

    float of[2][8][4];
    float mrun[2][2], lrun[2][2];
    #pragma unroll
    for (int r = 0; r < 2; r++) {
        mrun[r][0] = mrun[r][1] = -CUDART_INF_F;
        lrun[r][0] = lrun[r][1] = 0.0f;
        #pragma unroll
        for (int nt = 0; nt < 8; nt++)
            #pragma unroll
            for (int e = 0; e < 4; e++) of[r][nt][e] = 0.0f;
    }

    const int ktEnd = causal ? (2 * qt + 1) : (SEQ / 64 - 1);

    for (int kt = 0; kt <= ktEnd; kt++) {
        __syncthreads();   // prev iter done with Ks/Vs; also covers Q staging
        const float* Kt = Kg + (size_t)kt * 64 * DHEAD;
        const float* Vp = Vg + (size_t)kt * 64 * DHEAD;
        for (int i = tid; i < 64 * 16; i += 128) {
            const int r  = i >> 4;
            const int c4 = (i & 15) * 4;
            float4 kv = *(const float4*)(Kt + r * 64 + c4);
            float* kp = &Ks[r * KSTR + c4];
            kp[0] = tf32r(kv.x); kp[1] = tf32r(kv.y);
            kp[2] = tf32r(kv.z); kp[3] = tf32r(kv.w);
            float4 vv = *(const float4*)(Vp + r * 64 + c4);
            float* vp = &Vs[r * VSTR + c4];
            vp[0] = tf32r(vv.x); vp[1] = tf32r(vv.y);
            vp[2] = tf32r(vv.z); vp[3] = tf32r(vv.w);
        }
        __syncthreads();

        // ---- S = Qs K^T for BOTH row-blocks, K-frags hoisted ----
        float sf[2][8][4];
        #pragma unroll
        for (int r = 0; r < 2; r++)
            #pragma unroll
            for (int nt = 0; nt < 8; nt++)
                #pragma unroll
                for (int e = 0; e < 4; e++) sf[r][nt][e] = 0.0f;

        #pragma unroll
        for (int k8 = 0; k8 < 8; k8++) {
            uint32_t kb0[8], kb1[8];
            #pragma unroll
            for (int nt = 0; nt < 8; nt++) {
                const float* bb = &Ks[(nt * 8 + g) * KSTR + k8 * 8];
                kb0[nt] = fbits(bb[t]);
                kb1[nt] = fbits(bb[t + 4]);
            }
            #pragma unroll
            for (int r = 0; r < 2; r++) {
                const float* qb = &Qs[(w * 32 + r * 16) * KSTR + k8 * 8];
                const uint32_t a0 = fbits(qb[g * KSTR + t]);
                const uint32_t a1 = fbits(qb[(g + 8) * KSTR + t]);
                const uint32_t a2 = fbits(qb[g * KSTR + t + 4]);
                const uint32_t a3 = fbits(qb[(g + 8) * KSTR + t + 4]);
                #pragma unroll
                for (int nt = 0; nt < 8; nt++)
                    mma_tf32(sf[r][nt], a0, a1, a2, a3, kb0[nt], kb1[nt]);
            }
        }

        const bool diag = causal && (kt >= 2 * qt);

        #pragma unroll
        for (int r = 0; r < 2; r++) {
            // ---- causal mask ----
            if (diag) {
                const int rowb = qt * QTILE + w * 32 + r * 16;
                const int colb = kt * 64;
                #pragma unroll
                for (int nt = 0; nt < 8; nt++) {
                    #pragma unroll
                    for (int e = 0; e < 4; e++) {
                        const int col = colb + nt * 8 + 2 * t + (e & 1);
                        const int row = rowb + g + ((e >> 1) << 3);
                        if (col > row) sf[r][nt][e] = -CUDART_INF_F;
                    }
                }
            }

            // ---- online softmax in base 2 (rows: A = g, B = g+8) ----
            float mxA = -CUDART_INF_F, mxB = -CUDART_INF_F;
            #pragma unroll
            for (int nt = 0; nt < 8; nt++) {
                mxA = fmaxf(mxA, fmaxf(sf[r][nt][0], sf[r][nt][1]));
                mxB = fmaxf(mxB, fmaxf(sf[r][nt][2], sf[r][nt][3]));
            }
            mxA = fmaxf(mxA, __shfl_xor_sync(0xffffffffu, mxA, 1));
            mxA = fmaxf(mxA, __shfl_xor_sync(0xffffffffu, mxA, 2));
            mxB = fmaxf(mxB, __shfl_xor_sync(0xffffffffu, mxB, 1));
            mxB = fmaxf(mxB, __shfl_xor_sync(0xffffffffu, mxB, 2));

            const float mnA = fmaxf(mrun[r][0], mxA);
            const float mnB = fmaxf(mrun[r][1], mxB);
            const float aA = exp2f(mrun[r][0] - mnA);
            const float aB = exp2f(mrun[r][1] - mnB);
            float sA = 0.0f, sB = 0.0f;
            #pragma unroll
            for (int nt = 0; nt < 8; nt++) {
                sf[r][nt][0] = exp2f(sf[r][nt][0] - mnA);
                sf[r][nt][1] = exp2f(sf[r][nt][1] - mnA);
                sf[r][nt][2] = exp2f(sf[r][nt][2] - mnB);
                sf[r][nt][3] = exp2f(sf[r][nt][3] - mnB);
                sA += sf[r][nt][0] + sf[r][nt][1];
                sB += sf[r][nt][2] + sf[r][nt][3];
            }
            sA += __shfl_xor_sync(0xffffffffu, sA, 1);
            sA += __shfl_xor_sync(0xffffffffu, sA, 2);
            sB += __shfl_xor_sync(0xffffffffu, sB, 1);
            sB += __shfl_xor_sync(0xffffffffu, sB, 2);
            lrun[r][0] = lrun[r][0] * aA + sA;
            lrun[r][1] = lrun[r][1] * aB + sB;
            mrun[r][0] = mnA;
            mrun[r][1] = mnB;
            #pragma unroll
            for (int nt = 0; nt < 8; nt++) {
                of[r][nt][0] *= aA; of[r][nt][1] *= aA;
                of[r][nt][2] *= aB; of[r][nt][3] *= aB;
            }

            // ---- write P (warp-private rows) ----
            #pragma unroll
            for (int nt = 0; nt < 8; nt++) {
                const int c = nt * 8 + 2 * t;
                float* p0 = &Ps[(w * 32 + r * 16 + g) * KSTR + c];
                float* p1 = &Ps[(w * 32 + r * 16 + g + 8) * KSTR + c];
                p0[0] = tf32r(sf[r][nt][0]); p0[1] = tf32r(sf[r][nt][1]);
                p1[0] = tf32r(sf[r][nt][2]); p1[1] = tf32r(sf[r][nt][3]);
            }
        }
        __syncwarp();

        // ---- O += P V : V-frags hoisted across row-blocks ----
        #pragma unroll
        for (int k8 = 0; k8 < 8; k8++) {
            uint32_t vb0[8], vb1[8];
            #pragma unroll
            for (int nt = 0; nt < 8; nt++) {
                vb0[nt] = fbits(Vs[(k8 * 8 + t) * VSTR + nt * 8 + g]);
                vb1[nt] = fbits(Vs[(k8 * 8 + t + 4) * VSTR + nt * 8 + g]);
            }
            #pragma unroll
            for (int r = 0; r < 2; r++) {
                const float* base = &Ps[(w * 32 + r * 16) * KSTR + k8 * 8];
                const uint32_t a0 = fbits(base[g * KSTR + t]);
                const uint32_t a1 = fbits(base[(g + 8) * KSTR + t]);
                const uint32_t a2 = fbits(base[g * KSTR + t + 4]);
                const uint32_t a3 = fbits(base[(g + 8) * KSTR + t + 4]);
                #pragma unroll
                for (int nt = 0; nt < 8; nt++)
                    mma_tf32(of[r][nt], a0, a1, a2, a3, vb0[nt], vb1[nt]);
            }
        }
    }

    // ---- epilogue: normalize, store to g_attn [b, s, h*64+d] ----
    #pragma unroll
    for (int r = 0; r < 2; r++) {
        const float iA = 1.0f / lrun[r][0];
        const float iB = 1.0f / lrun[r][1];
        const int qrow = qt * QTILE + w * 32 + r * 16;
        #pragma unroll
        for (int nt = 0; nt < 8; nt++) {
            const int d = h * 64 + nt * 8 + 2 * t;
            float2 v0, v1;
            v0.x = of[r][nt][0] * iA; v0.y = of[r][nt][1] * iA;
            v1.x = of[r][nt][2] * iB; v1.y = of[r][nt][3] * iB;
            *(float2*)(g_attn + ((size_t)b * SEQ + qrow + g) * DMODEL + d) = v0;
            *(float2*)(g_attn + ((size_t)b * SEQ + qrow + g + 8) * DMODEL + d) = v1;
        }
    }
}

// ---------------------------------------------------------------------------
extern "C" void kernel_launch(void* const* d_in, const int* in_sizes, int n_in,
                              void* d_out, int out_size)
{
    const float* x   = (const float*)d_in[0];   // [4, 2048, 1024]
    const float* w1  = (const float*)d_in[1];   // [3072, 1024]
    const float* b1  = (const float*)d_in[2];   // [3072]
    const float* w2  = (const float*)d_in[3];   // [1024, 1024]
    const float* b2  = (const float*)d_in[4];   // [1024]
    const int*   msk = (const int*)  d_in[5];   // causal flag
    float* out = (float*)d_out;

    const int M = BATCH * SEQ;   // 8192

    cudaFuncSetAttribute(flash_mma,
                         cudaFuncAttributeMaxDynamicSharedMemorySize, FLASH_SMEM);

    // 1) QKV projection (mma.sync tf32, cp.async pipeline) -> g_q/g_k/g_v
    gemm_mma<0><<<dim3(3 * DMODEL / GBN, M / GBM), 256>>>(
        x, w1, b1, nullptr, M, 3 * DMODEL, DMODEL);

    // 2) Flash attention (mma.sync tf32) -> g_attn
    flash_mma<<<dim3(SEQ / QTILE, NHEADS, BATCH), 128, FLASH_SMEM>>>(msk);

    // 3) Output projection (mma.sync tf32, cp.async pipeline) -> d_out
    gemm_mma<1><<<dim3(DMODEL / GBN, M / GBM), 256>>>(
        nullptr, w2, b2, out, M, DMODEL, DMODEL);
}

// round 8
// speedup vs baseline: 1.5543x; 1.0610x over previous
#include <cuda_runtime.h>
#include <math.h>
#include <math_constants.h>
#include <cstdint>

#define BATCH  4
#define SEQ    2048
#define DMODEL 1024
#define NHEADS 16
#define DHEAD  64

// Scratch (device globals — allocation-free per harness rules)
__device__ float g_q[(size_t)BATCH * NHEADS * SEQ * DHEAD];
__device__ float g_k[(size_t)BATCH * NHEADS * SEQ * DHEAD];
__device__ float g_v[(size_t)BATCH * NHEADS * SEQ * DHEAD];
__device__ float g_attn[(size_t)BATCH * SEQ * DMODEL];
__device__ float g_xr[(size_t)BATCH * SEQ * DMODEL];        // x pre-rounded
__device__ float g_w1r[(size_t)3 * DMODEL * DMODEL];        // w1 pre-rounded
__device__ float g_w2r[(size_t)DMODEL * DMODEL];            // w2 pre-rounded

// ---------------------------------------------------------------------------
// helpers
// ---------------------------------------------------------------------------
__device__ __forceinline__ float tf32r(float x) {
    float r;
    asm("cvt.rna.tf32.f32 %0, %1;" : "=f"(r) : "f"(x));
    return r;
}

__device__ __forceinline__ uint32_t fbits(float x) { return __float_as_uint(x); }

__device__ __forceinline__ uint32_t smem_u32(const void* p) {
    uint32_t a;
    asm("{ .reg .u64 t; cvta.to.shared.u64 t, %1; cvt.u32.u64 %0, t; }"
        : "=r"(a) : "l"(p));
    return a;
}

__device__ __forceinline__ void cp16(uint32_t dst, const float* src) {
    asm volatile("cp.async.cg.shared.global [%0], [%1], 16;"
                 :: "r"(dst), "l"(src));
}

#define CP_COMMIT()  asm volatile("cp.async.commit_group;" ::: "memory")
#define CP_WAIT(n)   asm volatile("cp.async.wait_group %0;" :: "n"(n) : "memory")

// D = A(16x8 tf32, row) * B(8x8 tf32, col) + D   (f32 accum)
__device__ __forceinline__ void mma_tf32(float c[4],
                                         uint32_t a0, uint32_t a1,
                                         uint32_t a2, uint32_t a3,
                                         uint32_t b0, uint32_t b1) {
    asm volatile(
        "mma.sync.aligned.m16n8k8.row.col.f32.tf32.tf32.f32 "
        "{%0,%1,%2,%3}, {%4,%5,%6,%7}, {%8,%9}, {%0,%1,%2,%3};"
        : "+f"(c[0]), "+f"(c[1]), "+f"(c[2]), "+f"(c[3])
        : "r"(a0), "r"(a1), "r"(a2), "r"(a3), "r"(b0), "r"(b1));
}

// ---------------------------------------------------------------------------
// one-time TF32 pre-rounding pass (float4 grid-stride)
// ---------------------------------------------------------------------------
__global__ __launch_bounds__(256) void round_tf32_k(
    const float* __restrict__ s, float* __restrict__ d, int n4)
{
    int i = blockIdx.x * blockDim.x + threadIdx.x;
    if (i < n4) {
        float4 v = ((const float4*)s)[i];
        v.x = tf32r(v.x); v.y = tf32r(v.y);
        v.z = tf32r(v.z); v.w = tf32r(v.w);
        ((float4*)d)[i] = v;
    }
}

// ===========================================================================
// TF32 mma.sync GEMM (NT): C[m,n] = sum_k A[m,k] * W[n,k] + bias[n]
// 64x128x16 CTA tile, 256 thr = 8 warps (2m x 4n), warptile 32x32.
// 4-stage cp.async pipeline, ONE __syncthreads per stage.
// Inputs pre-rounded to TF32 — no CVT in inner loop.
// MODE 0: A = g_xr, scatter Q(scaled)/K/V rounded. MODE 1: A = g_attn.
// ===========================================================================
#define GBK  16
#define BKP  20
#define GBM  64
#define GBN  128
#define STG  4
#define GEMM_SMEM ((STG * GBM * BKP + STG * GBN * BKP) * 4)   // 61440

template <int MODE>
__global__ __launch_bounds__(256, 3) void gemm_mma(
    const float* __restrict__ A, const float* __restrict__ W,
    const float* __restrict__ bias, float* __restrict__ C,
    int M, int N, int K)
{
    extern __shared__ float smg[];
    float* As = smg;                          // [STG][GBM*BKP]
    float* Bs = smg + STG * GBM * BKP;        // [STG][GBN*BKP]

    const int tid  = threadIdx.x;
    const int lane = tid & 31;
    const int g    = lane >> 2;
    const int t    = lane & 3;
    const int wid  = tid >> 5;
    const int wm   = (wid >> 2) * 32;   // 0 / 32
    const int wn   = (wid & 3) * 32;    // 0 / 32 / 64 / 96
    const int bm   = blockIdx.y;
    const int bn   = blockIdx.x;

    const float* Ag = (MODE == 1) ? g_attn : g_xr;
    (void)A;

    // cp.async source rows/chunks
    const int arow = tid >> 2;            // 0..63
    const int ach  = (tid & 3) * 4;       // 0/4/8/12
    const float* Asrc = Ag + (size_t)(bm * GBM + arow) * K + ach;
    const int brow0 = tid >> 1;           // 0..127
    const int bch0  = (tid & 1) * 8;      // 0 / 8
    const float* Bsrc = W + (size_t)(bn * GBN + brow0) * K + bch0;

    const uint32_t aDst = smem_u32(As) + (arow * BKP + ach) * 4;
    const uint32_t bDst = smem_u32(Bs) + (brow0 * BKP + bch0) * 4;

    float acc[2][4][4];
    #pragma unroll
    for (int mt = 0; mt < 2; mt++)
        #pragma unroll
        for (int nt = 0; nt < 4; nt++)
            #pragma unroll
            for (int e = 0; e < 4; e++) acc[mt][nt][e] = 0.0f;

    const int NS = K / GBK;

    // ---- prologue: issue stages 0..2 ----
    #pragma unroll
    for (int st = 0; st < 3; st++) {
        const int k0 = st * GBK;
        cp16(aDst + st * GBM * BKP * 4, Asrc + k0);
        cp16(bDst + st * GBN * BKP * 4,      Bsrc + k0);
        cp16(bDst + st * GBN * BKP * 4 + 16, Bsrc + k0 + 4);
        CP_COMMIT();
    }

    for (int s = 0; s < NS; s++) {
        const int buf = s & 3;
        CP_WAIT(2);             // stage s complete (commit #s; 2 newer pending)
        __syncthreads();        // all warps done reading buf (s-1)%4

        if (s + 3 < NS) {       // refill buf (s+3)%4 == (s-1)%4
            const int nbuf = (s + 3) & 3;
            const int k0 = (s + 3) * GBK;
            cp16(aDst + nbuf * GBM * BKP * 4, Asrc + k0);
            cp16(bDst + nbuf * GBN * BKP * 4,      Bsrc + k0);
            cp16(bDst + nbuf * GBN * BKP * 4 + 16, Bsrc + k0 + 4);
        }
        CP_COMMIT();            // commit every iter (empty ok) to keep counts uniform

        const float* Asb = &As[buf * GBM * BKP];
        const float* Bsb = &Bs[buf * GBN * BKP];

        #pragma unroll
        for (int kk = 0; kk < 2; kk++) {
            uint32_t af[2][4];
            #pragma unroll
            for (int mt = 0; mt < 2; mt++) {
                const float* base = &Asb[(wm + mt * 16) * BKP + kk * 8];
                af[mt][0] = fbits(base[g * BKP + t]);
                af[mt][1] = fbits(base[(g + 8) * BKP + t]);
                af[mt][2] = fbits(base[g * BKP + t + 4]);
                af[mt][3] = fbits(base[(g + 8) * BKP + t + 4]);
            }
            #pragma unroll
            for (int nt = 0; nt < 4; nt++) {
                const float* bb = &Bsb[(wn + nt * 8 + g) * BKP + kk * 8];
                const uint32_t b0 = fbits(bb[t]);
                const uint32_t b1 = fbits(bb[t + 4]);
                #pragma unroll
                for (int mt = 0; mt < 2; mt++)
                    mma_tf32(acc[mt][nt], af[mt][0], af[mt][1], af[mt][2], af[mt][3],
                             b0, b1);
            }
        }
    }

    // ---- epilogue ----
    const float QSC = 0.125f * 1.4426950408889634f;
    #pragma unroll
    for (int mt = 0; mt < 2; mt++) {
        #pragma unroll
        for (int half = 0; half < 2; half++) {        // rows g / g+8
            const int m = bm * GBM + wm + mt * 16 + g + half * 8;
            const int bb_ = m >> 11;
            const int srow = m & 2047;
            #pragma unroll
            for (int nt = 0; nt < 4; nt++) {
                const int n = bn * GBN + wn + nt * 8 + 2 * t;
                float2 bvv = *(const float2*)(bias + n);
                float2 v;
                v.x = acc[mt][nt][half * 2 + 0] + bvv.x;
                v.y = acc[mt][nt][half * 2 + 1] + bvv.y;
                if (MODE == 0) {
                    const int part = n >> 10;
                    const int hd = n & 1023;
                    const int hh = hd >> 6;
                    const int d = hd & 63;
                    float* dst;
                    if (part == 0) {        // Q: fold softmax scale + round
                        dst = g_q;
                        v.x = tf32r(v.x * QSC);
                        v.y = tf32r(v.y * QSC);
                    } else {                // K / V: round
                        dst = (part == 1) ? g_k : g_v;
                        v.x = tf32r(v.x);
                        v.y = tf32r(v.y);
                    }
                    *(float2*)(dst + (((size_t)(bb_ * NHEADS + hh)) * SEQ + srow) * DHEAD + d) = v;
                } else {
                    *(float2*)(C + (size_t)m * N + n) = v;
                }
            }
        }
    }
}

// ===========================================================================
// Flash attention on mma.sync TF32 (128-row q-tile).
// Q/K/V arrive pre-rounded (Q pre-scaled) -> staging is raw cp.async copies.
// CTA = (b, h, 128-row q-tile), 128 thr = 4 warps, warp owns 32 q-rows.
// Base-2 softmax. Qs[128][68]; Ks[64][68]; Vs[64][72]; Ps[128][68].
// ===========================================================================
#define KSTR 68
#define VSTR 72
#define QTILE 128
#define FLASH_SMEM ((64 * KSTR + 64 * VSTR + QTILE * KSTR + QTILE * KSTR) * 4)

__global__ __launch_bounds__(128) void flash_mma(const int* __restrict__ maskFlag)
{
    extern __shared__ float smf[];
    float* Ks = smf;                    // [64 keys][KSTR]
    float* Vs = Ks + 64 * KSTR;         // [64 keys][VSTR]
    float* Qs = Vs + 64 * VSTR;         // [128 q][KSTR]   (persistent)
    float* Ps = Qs + QTILE * KSTR;      // [128 q][KSTR]

    const int tid  = threadIdx.x;
    const int lane = tid & 31;
    const int w    = tid >> 5;
    const int g    = lane >> 2;
    const int t    = lane & 3;
    const int qt   = (int)gridDim.x - 1 - (int)blockIdx.x;  // heavy tiles first
    const int h    = blockIdx.y;
    const int b    = blockIdx.z;
    const int causal = maskFlag[0];

    const size_t bh = (size_t)(b * NHEADS + h) * SEQ * DHEAD;
    const float* Qg = g_q + bh + (size_t)qt * QTILE * DHEAD;
    const float* Kg = g_k + bh;
    const float* Vg = g_v + bh;

    const uint32_t ksU = smem_u32(Ks);
    const uint32_t vsU = smem_u32(Vs);
    const uint32_t qsU = smem_u32(Qs);

    // ---- stage Q via cp.async (already scaled+rounded) ----
    #pragma unroll
    for (int j = 0; j < 16; j++) {
        const int i = tid + j * 128;
        const int r  = i >> 4;
        const int c4 = (i & 15) * 4;
        cp16(qsU + (r * KSTR + c4) * 4, Qg + r * 64 + c4);
    }
    CP_COMMIT();

    float of[2][8][4];
    float mrun[2][2], lrun[2][2];
    #pragma unroll
    for (int r = 0; r < 2; r++) {
        mrun[r][0] = mrun[r][1] = -CUDART_INF_F;
        lrun[r][0] = lrun[r][1] = 0.0f;
        #pragma unroll
        for (int nt = 0; nt < 8; nt++)
            #pragma unroll
            for (int e = 0; e < 4; e++) of[r][nt][e] = 0.0f;
    }

    const int ktEnd = causal ? (2 * qt + 1) : (SEQ / 64 - 1);

    for (int kt = 0; kt <= ktEnd; kt++) {
        __syncthreads();   // prev iter done reading Ks/Vs
        const float* Kt = Kg + (size_t)kt * 64 * DHEAD;
        const float* Vp = Vg + (size_t)kt * 64 * DHEAD;
        #pragma unroll
        for (int j = 0; j < 8; j++) {
            const int i = tid + j * 128;
            const int r  = i >> 4;
            const int c4 = (i & 15) * 4;
            cp16(ksU + (r * KSTR + c4) * 4, Kt + r * 64 + c4);
            cp16(vsU + (r * VSTR + c4) * 4, Vp + r * 64 + c4);
        }
        CP_COMMIT();
        CP_WAIT(0);
        __syncthreads();

        // ---- S = Qs K^T for BOTH row-blocks, K-frags hoisted ----
        float sf[2][8][4];
        #pragma unroll
        for (int r = 0; r < 2; r++)
            #pragma unroll
            for (int nt = 0; nt < 8; nt++)
                #pragma unroll
                for (int e = 0; e < 4; e++) sf[r][nt][e] = 0.0f;

        #pragma unroll
        for (int k8 = 0; k8 < 8; k8++) {
            uint32_t kb0[8], kb1[8];
            #pragma unroll
            for (int nt = 0; nt < 8; nt++) {
                const float* bb = &Ks[(nt * 8 + g) * KSTR + k8 * 8];
                kb0[nt] = fbits(bb[t]);
                kb1[nt] = fbits(bb[t + 4]);
            }
            #pragma unroll
            for (int r = 0; r < 2; r++) {
                const float* qb = &Qs[(w * 32 + r * 16) * KSTR + k8 * 8];
                const uint32_t a0 = fbits(qb[g * KSTR + t]);
                const uint32_t a1 = fbits(qb[(g + 8) * KSTR + t]);
                const uint32_t a2 = fbits(qb[g * KSTR + t + 4]);
                const uint32_t a3 = fbits(qb[(g + 8) * KSTR + t + 4]);
                #pragma unroll
                for (int nt = 0; nt < 8; nt++)
                    mma_tf32(sf[r][nt], a0, a1, a2, a3, kb0[nt], kb1[nt]);
            }
        }

        const bool diag = causal && (kt >= 2 * qt);

        #pragma unroll
        for (int r = 0; r < 2; r++) {
            // ---- causal mask ----
            if (diag) {
                const int rowb = qt * QTILE + w * 32 + r * 16;
                const int colb = kt * 64;
                #pragma unroll
                for (int nt = 0; nt < 8; nt++) {
                    #pragma unroll
                    for (int e = 0; e < 4; e++) {
                        const int col = colb + nt * 8 + 2 * t + (e & 1);
                        const int row = rowb + g + ((e >> 1) << 3);
                        if (col > row) sf[r][nt][e] = -CUDART_INF_F;
                    }
                }
            }

            // ---- online softmax in base 2 (rows: A = g, B = g+8) ----
            float mxA = -CUDART_INF_F, mxB = -CUDART_INF_F;
            #pragma unroll
            for (int nt = 0; nt < 8; nt++) {
                mxA = fmaxf(mxA, fmaxf(sf[r][nt][0], sf[r][nt][1]));
                mxB = fmaxf(mxB, fmaxf(sf[r][nt][2], sf[r][nt][3]));
            }
            mxA = fmaxf(mxA, __shfl_xor_sync(0xffffffffu, mxA, 1));
            mxA = fmaxf(mxA, __shfl_xor_sync(0xffffffffu, mxA, 2));
            mxB = fmaxf(mxB, __shfl_xor_sync(0xffffffffu, mxB, 1));
            mxB = fmaxf(mxB, __shfl_xor_sync(0xffffffffu, mxB, 2));

            const float mnA = fmaxf(mrun[r][0], mxA);
            const float mnB = fmaxf(mrun[r][1], mxB);
            const float aA = exp2f(mrun[r][0] - mnA);
            const float aB = exp2f(mrun[r][1] - mnB);
            float sA = 0.0f, sB = 0.0f;
            #pragma unroll
            for (int nt = 0; nt < 8; nt++) {
                sf[r][nt][0] = exp2f(sf[r][nt][0] - mnA);
                sf[r][nt][1] = exp2f(sf[r][nt][1] - mnA);
                sf[r][nt][2] = exp2f(sf[r][nt][2] - mnB);
                sf[r][nt][3] = exp2f(sf[r][nt][3] - mnB);
                sA += sf[r][nt][0] + sf[r][nt][1];
                sB += sf[r][nt][2] + sf[r][nt][3];
            }
            sA += __shfl_xor_sync(0xffffffffu, sA, 1);
            sA += __shfl_xor_sync(0xffffffffu, sA, 2);
            sB += __shfl_xor_sync(0xffffffffu, sB, 1);
            sB += __shfl_xor_sync(0xffffffffu, sB, 2);
            lrun[r][0] = lrun[r][0] * aA + sA;
            lrun[r][1] = lrun[r][1] * aB + sB;
            mrun[r][0] = mnA;
            mrun[r][1] = mnB;
            #pragma unroll
            for (int nt = 0; nt < 8; nt++) {
                of[r][nt][0] *= aA; of[r][nt][1] *= aA;
                of[r][nt][2] *= aB; of[r][nt][3] *= aB;
            }

            // ---- write P (warp-private rows) ----
            #pragma unroll
            for (int nt = 0; nt < 8; nt++) {
                const int c = nt * 8 + 2 * t;
                float* p0 = &Ps[(w * 32 + r * 16 + g) * KSTR + c];
                float* p1 = &Ps[(w * 32 + r * 16 + g + 8) * KSTR + c];
                p0[0] = tf32r(sf[r][nt][0]); p0[1] = tf32r(sf[r][nt][1]);
                p1[0] = tf32r(sf[r][nt][2]); p1[1] = tf32r(sf[r][nt][3]);
            }
        }
        __syncwarp();

        // ---- O += P V : V-frags hoisted across row-blocks ----
        #pragma unroll
        for (int k8 = 0; k8 < 8; k8++) {
            uint32_t vb0[8], vb1[8];
            #pragma unroll
            for (int nt = 0; nt < 8; nt++) {
                vb0[nt] = fbits(Vs[(k8 * 8 + t) * VSTR + nt * 8 + g]);
                vb1[nt] = fbits(Vs[(k8 * 8 + t + 4) * VSTR + nt * 8 + g]);
            }
            #pragma unroll
            for (int r = 0; r < 2; r++) {
                const float* base = &Ps[(w * 32 + r * 16) * KSTR + k8 * 8];
                const uint32_t a0 = fbits(base[g * KSTR + t]);
                const uint32_t a1 = fbits(base[(g + 8) * KSTR + t]);
                const uint32_t a2 = fbits(base[g * KSTR + t + 4]);
                const uint32_t a3 = fbits(base[(g + 8) * KSTR + t + 4]);
                #pragma unroll
                for (int nt = 0; nt < 8; nt++)
                    mma_tf32(of[r][nt], a0, a1, a2, a3, vb0[nt], vb1[nt]);
            }
        }
    }

    // ---- epilogue: normalize, round (A-operand of out-proj), store ----
    #pragma unroll
    for (int r = 0; r < 2; r++) {
        const float iA = 1.0f / lrun[r][0];
        const float iB = 1.0f / lrun[r][1];
        const int qrow = qt * QTILE + w * 32 + r * 16;
        #pragma unroll
        for (int nt = 0; nt < 8; nt++) {
            const int d = h * 64 + nt * 8 + 2 * t;
            float2 v0, v1;
            v0.x = tf32r(of[r][nt][0] * iA); v0.y = tf32r(of[r][nt][1] * iA);
            v1.x = tf32r(of[r][nt][2] * iB); v1.y = tf32r(of[r][nt][3] * iB);
            *(float2*)(g_attn + ((size_t)b * SEQ + qrow + g) * DMODEL + d) = v0;
            *(float2*)(g_attn + ((size_t)b * SEQ + qrow + g + 8) * DMODEL + d) = v1;
        }
    }
}

// ---------------------------------------------------------------------------
extern "C" void kernel_launch(void* const* d_in, const int* in_sizes, int n_in,
                              void* d_out, int out_size)
{
    const float* x   = (const float*)d_in[0];   // [4, 2048, 1024]
    const float* w1  = (const float*)d_in[1];   // [3072, 1024]
    const float* b1  = (const float*)d_in[2];   // [3072]
    const float* w2  = (const float*)d_in[3];   // [1024, 1024]
    const float* b2  = (const float*)d_in[4];   // [1024]
    const int*   msk = (const int*)  d_in[5];   // causal flag
    float* out = (float*)d_out;

    const int M = BATCH * SEQ;   // 8192

    cudaFuncSetAttribute(gemm_mma<0>,
                         cudaFuncAttributeMaxDynamicSharedMemorySize, GEMM_SMEM);
    cudaFuncSetAttribute(gemm_mma<1>,
                         cudaFuncAttributeMaxDynamicSharedMemorySize, GEMM_SMEM);
    cudaFuncSetAttribute(flash_mma,
                         cudaFuncAttributeMaxDynamicSharedMemorySize, FLASH_SMEM);

    // 0) pre-round inputs to TF32 (one cheap pass)
    float* d_xr;  cudaGetSymbolAddress((void**)&d_xr,  g_xr);
    float* d_w1r; cudaGetSymbolAddress((void**)&d_w1r, g_w1r);
    float* d_w2r; cudaGetSymbolAddress((void**)&d_w2r, g_w2r);
    {
        const int nx = M * DMODEL / 4;              // 2M float4
        round_tf32_k<<<(nx + 255) / 256, 256>>>(x, d_xr, nx);
        const int n1 = 3 * DMODEL * DMODEL / 4;
        round_tf32_k<<<(n1 + 255) / 256, 256>>>(w1, d_w1r, n1);
        const int n2 = DMODEL * DMODEL / 4;
        round_tf32_k<<<(n2 + 255) / 256, 256>>>(w2, d_w2r, n2);
    }

    // 1) QKV projection -> g_q (scaled+rounded) / g_k / g_v (rounded)
    gemm_mma<0><<<dim3(3 * DMODEL / GBN, M / GBM), 256, GEMM_SMEM>>>(
        d_xr, d_w1r, b1, nullptr, M, 3 * DMODEL, DMODEL);

    // 2) Flash attention -> g_attn (rounded)
    flash_mma<<<dim3(SEQ / QTILE, NHEADS, BATCH), 128, FLASH_SMEM>>>(msk);

    // 3) Output projection -> d_out
    gemm_mma<1><<<dim3(DMODEL / GBN, M / GBM), 256, GEMM_SMEM>>>(
        nullptr, d_w2r, b2, out, M, DMODEL, DMODEL);
}

// round 9
// speedup vs baseline: 1.5925x; 1.0246x over previous
#include <cuda_runtime.h>
#include <math.h>
#include <math_constants.h>
#include <cstdint>

#define BATCH  4
#define SEQ    2048
#define DMODEL 1024
#define NHEADS 16
#define DHEAD  64

// Scratch (device globals — allocation-free per harness rules)
__device__ float g_q[(size_t)BATCH * NHEADS * SEQ * DHEAD];
__device__ float g_k[(size_t)BATCH * NHEADS * SEQ * DHEAD];
__device__ float g_v[(size_t)BATCH * NHEADS * SEQ * DHEAD];
__device__ float g_attn[(size_t)BATCH * SEQ * DMODEL];
__device__ float g_xr[(size_t)BATCH * SEQ * DMODEL];        // x pre-rounded
__device__ float g_w1r[(size_t)3 * DMODEL * DMODEL];        // w1 pre-rounded
__device__ float g_w2r[(size_t)DMODEL * DMODEL];            // w2 pre-rounded

// ---------------------------------------------------------------------------
// helpers
// ---------------------------------------------------------------------------
__device__ __forceinline__ float tf32r(float x) {
    float r;
    asm("cvt.rna.tf32.f32 %0, %1;" : "=f"(r) : "f"(x));
    return r;
}

__device__ __forceinline__ uint32_t fbits(float x) { return __float_as_uint(x); }

__device__ __forceinline__ uint32_t smem_u32(const void* p) {
    uint32_t a;
    asm("{ .reg .u64 t; cvta.to.shared.u64 t, %1; cvt.u32.u64 %0, t; }"
        : "=r"(a) : "l"(p));
    return a;
}

__device__ __forceinline__ void cp16(uint32_t dst, const float* src) {
    asm volatile("cp.async.cg.shared.global [%0], [%1], 16;"
                 :: "r"(dst), "l"(src));
}

#define CP_COMMIT()  asm volatile("cp.async.commit_group;" ::: "memory")
#define CP_WAIT(n)   asm volatile("cp.async.wait_group %0;" :: "n"(n) : "memory")

// D = A(16x8 tf32, row) * B(8x8 tf32, col) + D   (f32 accum)
__device__ __forceinline__ void mma_tf32(float c[4],
                                         uint32_t a0, uint32_t a1,
                                         uint32_t a2, uint32_t a3,
                                         uint32_t b0, uint32_t b1) {
    asm volatile(
        "mma.sync.aligned.m16n8k8.row.col.f32.tf32.tf32.f32 "
        "{%0,%1,%2,%3}, {%4,%5,%6,%7}, {%8,%9}, {%0,%1,%2,%3};"
        : "+f"(c[0]), "+f"(c[1]), "+f"(c[2]), "+f"(c[3])
        : "r"(a0), "r"(a1), "r"(a2), "r"(a3), "r"(b0), "r"(b1));
}

// ---------------------------------------------------------------------------
// one-time TF32 pre-rounding pass (float4 grid-stride)
// ---------------------------------------------------------------------------
__global__ __launch_bounds__(256) void round_tf32_k(
    const float* __restrict__ s, float* __restrict__ d, int n4)
{
    int i = blockIdx.x * blockDim.x + threadIdx.x;
    if (i < n4) {
        float4 v = ((const float4*)s)[i];
        v.x = tf32r(v.x); v.y = tf32r(v.y);
        v.z = tf32r(v.z); v.w = tf32r(v.w);
        ((float4*)d)[i] = v;
    }
}

// ===========================================================================
// TF32 mma.sync GEMM (NT): C[m,n] = sum_k A[m,k] * W[n,k] + bias[n]
// 128x128x16 CTA tile, 256 thr = 8 warps (4m x 2n), warptile 32x64.
// 4-stage cp.async pipeline, ONE __syncthreads per stage.
// Inputs pre-rounded to TF32 — no CVT in inner loop.
// MODE 0: A = g_xr, scatter Q(scaled)/K/V rounded. MODE 1: A = g_attn.
// ===========================================================================
#define GBK  16
#define BKP  20
#define GBM  128
#define GBN  128
#define STG  4
#define GEMM_SMEM ((STG * GBM * BKP + STG * GBN * BKP) * 4)   // 81920

template <int MODE>
__global__ __launch_bounds__(256, 2) void gemm_mma(
    const float* __restrict__ A, const float* __restrict__ W,
    const float* __restrict__ bias, float* __restrict__ C,
    int M, int N, int K)
{
    extern __shared__ float smg[];
    float* As = smg;                          // [STG][GBM*BKP]
    float* Bs = smg + STG * GBM * BKP;        // [STG][GBN*BKP]

    const int tid  = threadIdx.x;
    const int lane = tid & 31;
    const int g    = lane >> 2;
    const int t    = lane & 3;
    const int wid  = tid >> 5;
    const int wm   = (wid & 3) * 32;    // 0/32/64/96
    const int wn   = (wid >> 2) * 64;   // 0/64
    const int bm   = blockIdx.y;
    const int bn   = blockIdx.x;

    const float* Ag = (MODE == 1) ? g_attn : g_xr;
    (void)A;

    // cp.async staging: thread owns row tid>>1, floats (tid&1)*8 .. +7 (2 cp16)
    const int srow = tid >> 1;
    const int sch  = (tid & 1) * 8;
    const float* Asrc = Ag + (size_t)(bm * GBM + srow) * K + sch;
    const float* Bsrc = W  + (size_t)(bn * GBN + srow) * K + sch;

    const uint32_t aDst = smem_u32(As) + (srow * BKP + sch) * 4;
    const uint32_t bDst = smem_u32(Bs) + (srow * BKP + sch) * 4;

    float acc[2][8][4];
    #pragma unroll
    for (int mt = 0; mt < 2; mt++)
        #pragma unroll
        for (int nt = 0; nt < 8; nt++)
            #pragma unroll
            for (int e = 0; e < 4; e++) acc[mt][nt][e] = 0.0f;

    const int NS = K / GBK;

    // ---- prologue: issue stages 0..2 ----
    #pragma unroll
    for (int st = 0; st < 3; st++) {
        const int k0 = st * GBK;
        cp16(aDst + st * GBM * BKP * 4,      Asrc + k0);
        cp16(aDst + st * GBM * BKP * 4 + 16, Asrc + k0 + 4);
        cp16(bDst + st * GBN * BKP * 4,      Bsrc + k0);
        cp16(bDst + st * GBN * BKP * 4 + 16, Bsrc + k0 + 4);
        CP_COMMIT();
    }

    for (int s = 0; s < NS; s++) {
        const int buf = s & 3;
        CP_WAIT(2);             // stage s complete
        __syncthreads();        // all warps done reading buf (s-1)%4

        if (s + 3 < NS) {
            const int nbuf = (s + 3) & 3;
            const int k0 = (s + 3) * GBK;
            cp16(aDst + nbuf * GBM * BKP * 4,      Asrc + k0);
            cp16(aDst + nbuf * GBM * BKP * 4 + 16, Asrc + k0 + 4);
            cp16(bDst + nbuf * GBN * BKP * 4,      Bsrc + k0);
            cp16(bDst + nbuf * GBN * BKP * 4 + 16, Bsrc + k0 + 4);
        }
        CP_COMMIT();            // uniform commit count

        const float* Asb = &As[buf * GBM * BKP];
        const float* Bsb = &Bs[buf * GBN * BKP];

        #pragma unroll
        for (int kk = 0; kk < 2; kk++) {
            uint32_t af[2][4];
            #pragma unroll
            for (int mt = 0; mt < 2; mt++) {
                const float* base = &Asb[(wm + mt * 16) * BKP + kk * 8];
                af[mt][0] = fbits(base[g * BKP + t]);
                af[mt][1] = fbits(base[(g + 8) * BKP + t]);
                af[mt][2] = fbits(base[g * BKP + t + 4]);
                af[mt][3] = fbits(base[(g + 8) * BKP + t + 4]);
            }
            #pragma unroll
            for (int nt = 0; nt < 8; nt++) {
                const float* bb = &Bsb[(wn + nt * 8 + g) * BKP + kk * 8];
                const uint32_t b0 = fbits(bb[t]);
                const uint32_t b1 = fbits(bb[t + 4]);
                #pragma unroll
                for (int mt = 0; mt < 2; mt++)
                    mma_tf32(acc[mt][nt], af[mt][0], af[mt][1], af[mt][2], af[mt][3],
                             b0, b1);
            }
        }
    }

    // ---- epilogue ----
    const float QSC = 0.125f * 1.4426950408889634f;
    #pragma unroll
    for (int mt = 0; mt < 2; mt++) {
        #pragma unroll
        for (int half = 0; half < 2; half++) {        // rows g / g+8
            const int m = bm * GBM + wm + mt * 16 + g + half * 8;
            const int bb_ = m >> 11;
            const int srw = m & 2047;
            #pragma unroll
            for (int nt = 0; nt < 8; nt++) {
                const int n = bn * GBN + wn + nt * 8 + 2 * t;
                float2 bvv = *(const float2*)(bias + n);
                float2 v;
                v.x = acc[mt][nt][half * 2 + 0] + bvv.x;
                v.y = acc[mt][nt][half * 2 + 1] + bvv.y;
                if (MODE == 0) {
                    const int part = n >> 10;
                    const int hd = n & 1023;
                    const int hh = hd >> 6;
                    const int d = hd & 63;
                    float* dst;
                    if (part == 0) {        // Q: fold softmax scale + round
                        dst = g_q;
                        v.x = tf32r(v.x * QSC);
                        v.y = tf32r(v.y * QSC);
                    } else {                // K / V: round
                        dst = (part == 1) ? g_k : g_v;
                        v.x = tf32r(v.x);
                        v.y = tf32r(v.y);
                    }
                    *(float2*)(dst + (((size_t)(bb_ * NHEADS + hh)) * SEQ + srw) * DHEAD + d) = v;
                } else {
                    *(float2*)(C + (size_t)m * N + n) = v;
                }
            }
        }
    }
}

// ===========================================================================
// Flash attention on mma.sync TF32 (128-row q-tile, 8 warps x 16 rows).
// Q/K/V arrive pre-rounded (Q pre-scaled) -> staging is raw cp.async copies.
// Base-2 softmax. Qs[128][68]; Ks[64][68]; Vs[64][72]; Ps[128][68].
// ===========================================================================
#define KSTR 68
#define VSTR 72
#define QTILE 128
#define FLASH_SMEM ((64 * KSTR + 64 * VSTR + QTILE * KSTR + QTILE * KSTR) * 4)

__global__ __launch_bounds__(256) void flash_mma(const int* __restrict__ maskFlag)
{
    extern __shared__ float smf[];
    float* Ks = smf;                    // [64 keys][KSTR]
    float* Vs = Ks + 64 * KSTR;         // [64 keys][VSTR]
    float* Qs = Vs + 64 * VSTR;         // [128 q][KSTR]   (persistent)
    float* Ps = Qs + QTILE * KSTR;      // [128 q][KSTR]

    const int tid  = threadIdx.x;
    const int lane = tid & 31;
    const int w    = tid >> 5;          // 0..7, owns q-rows [w*16, w*16+16)
    const int g    = lane >> 2;
    const int t    = lane & 3;
    const int qt   = (int)gridDim.x - 1 - (int)blockIdx.x;  // heavy tiles first
    const int h    = blockIdx.y;
    const int b    = blockIdx.z;
    const int causal = maskFlag[0];

    const size_t bh = (size_t)(b * NHEADS + h) * SEQ * DHEAD;
    const float* Qg = g_q + bh + (size_t)qt * QTILE * DHEAD;
    const float* Kg = g_k + bh;
    const float* Vg = g_v + bh;

    const uint32_t ksU = smem_u32(Ks);
    const uint32_t vsU = smem_u32(Vs);
    const uint32_t qsU = smem_u32(Qs);

    // ---- stage Q via cp.async (already scaled+rounded) ----
    #pragma unroll
    for (int j = 0; j < 8; j++) {
        const int i = tid + j * 256;
        const int r  = i >> 4;
        const int c4 = (i & 15) * 4;
        cp16(qsU + (r * KSTR + c4) * 4, Qg + r * 64 + c4);
    }
    CP_COMMIT();

    float of[8][4];
    float mA = -CUDART_INF_F, mB = -CUDART_INF_F;
    float lA = 0.0f, lB = 0.0f;
    #pragma unroll
    for (int nt = 0; nt < 8; nt++)
        #pragma unroll
        for (int e = 0; e < 4; e++) of[nt][e] = 0.0f;

    const int ktEnd = causal ? (2 * qt + 1) : (SEQ / 64 - 1);

    for (int kt = 0; kt <= ktEnd; kt++) {
        __syncthreads();   // prev iter done reading Ks/Vs
        const float* Kt = Kg + (size_t)kt * 64 * DHEAD;
        const float* Vp = Vg + (size_t)kt * 64 * DHEAD;
        #pragma unroll
        for (int j = 0; j < 4; j++) {
            const int i = tid + j * 256;
            const int r  = i >> 4;
            const int c4 = (i & 15) * 4;
            cp16(ksU + (r * KSTR + c4) * 4, Kt + r * 64 + c4);
            cp16(vsU + (r * VSTR + c4) * 4, Vp + r * 64 + c4);
        }
        CP_COMMIT();
        CP_WAIT(0);
        __syncthreads();

        // ---- S = Qs K^T (m16 x n64, k=64) ----
        float sf[8][4];
        #pragma unroll
        for (int nt = 0; nt < 8; nt++)
            #pragma unroll
            for (int e = 0; e < 4; e++) sf[nt][e] = 0.0f;

        #pragma unroll
        for (int k8 = 0; k8 < 8; k8++) {
            const float* qb = &Qs[(w * 16) * KSTR + k8 * 8];
            const uint32_t a0 = fbits(qb[g * KSTR + t]);
            const uint32_t a1 = fbits(qb[(g + 8) * KSTR + t]);
            const uint32_t a2 = fbits(qb[g * KSTR + t + 4]);
            const uint32_t a3 = fbits(qb[(g + 8) * KSTR + t + 4]);
            #pragma unroll
            for (int nt = 0; nt < 8; nt++) {
                const float* bb = &Ks[(nt * 8 + g) * KSTR + k8 * 8];
                mma_tf32(sf[nt], a0, a1, a2, a3, fbits(bb[t]), fbits(bb[t + 4]));
            }
        }

        // ---- causal mask ----
        if (causal && (kt >= 2 * qt)) {
            const int rowb = qt * QTILE + w * 16;
            const int colb = kt * 64;
            #pragma unroll
            for (int nt = 0; nt < 8; nt++) {
                #pragma unroll
                for (int e = 0; e < 4; e++) {
                    const int col = colb + nt * 8 + 2 * t + (e & 1);
                    const int row = rowb + g + ((e >> 1) << 3);
                    if (col > row) sf[nt][e] = -CUDART_INF_F;
                }
            }
        }

        // ---- online softmax in base 2 (rows: A = g, B = g+8) ----
        float mxA = -CUDART_INF_F, mxB = -CUDART_INF_F;
        #pragma unroll
        for (int nt = 0; nt < 8; nt++) {
            mxA = fmaxf(mxA, fmaxf(sf[nt][0], sf[nt][1]));
            mxB = fmaxf(mxB, fmaxf(sf[nt][2], sf[nt][3]));
        }
        mxA = fmaxf(mxA, __shfl_xor_sync(0xffffffffu, mxA, 1));
        mxA = fmaxf(mxA, __shfl_xor_sync(0xffffffffu, mxA, 2));
        mxB = fmaxf(mxB, __shfl_xor_sync(0xffffffffu, mxB, 1));
        mxB = fmaxf(mxB, __shfl_xor_sync(0xffffffffu, mxB, 2));

        const float mnA = fmaxf(mA, mxA);
        const float mnB = fmaxf(mB, mxB);
        const float aA = exp2f(mA - mnA);
        const float aB = exp2f(mB - mnB);
        float sA = 0.0f, sB = 0.0f;
        #pragma unroll
        for (int nt = 0; nt < 8; nt++) {
            sf[nt][0] = exp2f(sf[nt][0] - mnA);
            sf[nt][1] = exp2f(sf[nt][1] - mnA);
            sf[nt][2] = exp2f(sf[nt][2] - mnB);
            sf[nt][3] = exp2f(sf[nt][3] - mnB);
            sA += sf[nt][0] + sf[nt][1];
            sB += sf[nt][2] + sf[nt][3];
        }
        sA += __shfl_xor_sync(0xffffffffu, sA, 1);
        sA += __shfl_xor_sync(0xffffffffu, sA, 2);
        sB += __shfl_xor_sync(0xffffffffu, sB, 1);
        sB += __shfl_xor_sync(0xffffffffu, sB, 2);
        lA = lA * aA + sA;
        lB = lB * aB + sB;
        mA = mnA;
        mB = mnB;
        #pragma unroll
        for (int nt = 0; nt < 8; nt++) {
            of[nt][0] *= aA; of[nt][1] *= aA;
            of[nt][2] *= aB; of[nt][3] *= aB;
        }

        // ---- write P (warp-private rows) ----
        #pragma unroll
        for (int nt = 0; nt < 8; nt++) {
            const int c = nt * 8 + 2 * t;
            float* p0 = &Ps[(w * 16 + g) * KSTR + c];
            float* p1 = &Ps[(w * 16 + g + 8) * KSTR + c];
            p0[0] = tf32r(sf[nt][0]); p0[1] = tf32r(sf[nt][1]);
            p1[0] = tf32r(sf[nt][2]); p1[1] = tf32r(sf[nt][3]);
        }
        __syncwarp();

        // ---- O += P V (m16 x n64, k=64) ----
        #pragma unroll
        for (int k8 = 0; k8 < 8; k8++) {
            const float* base = &Ps[(w * 16) * KSTR + k8 * 8];
            const uint32_t a0 = fbits(base[g * KSTR + t]);
            const uint32_t a1 = fbits(base[(g + 8) * KSTR + t]);
            const uint32_t a2 = fbits(base[g * KSTR + t + 4]);
            const uint32_t a3 = fbits(base[(g + 8) * KSTR + t + 4]);
            #pragma unroll
            for (int nt = 0; nt < 8; nt++) {
                const uint32_t b0 = fbits(Vs[(k8 * 8 + t) * VSTR + nt * 8 + g]);
                const uint32_t b1 = fbits(Vs[(k8 * 8 + t + 4) * VSTR + nt * 8 + g]);
                mma_tf32(of[nt], a0, a1, a2, a3, b0, b1);
            }
        }
    }

    // ---- epilogue: normalize, round (A-operand of out-proj), store ----
    const float iA = 1.0f / lA;
    const float iB = 1.0f / lB;
    const int qrow = qt * QTILE + w * 16;
    #pragma unroll
    for (int nt = 0; nt < 8; nt++) {
        const int d = h * 64 + nt * 8 + 2 * t;
        float2 v0, v1;
        v0.x = tf32r(of[nt][0] * iA); v0.y = tf32r(of[nt][1] * iA);
        v1.x = tf32r(of[nt][2] * iB); v1.y = tf32r(of[nt][3] * iB);
        *(float2*)(g_attn + ((size_t)b * SEQ + qrow + g) * DMODEL + d) = v0;
        *(float2*)(g_attn + ((size_t)b * SEQ + qrow + g + 8) * DMODEL + d) = v1;
    }
}

// ---------------------------------------------------------------------------
extern "C" void kernel_launch(void* const* d_in, const int* in_sizes, int n_in,
                              void* d_out, int out_size)
{
    const float* x   = (const float*)d_in[0];   // [4, 2048, 1024]
    const float* w1  = (const float*)d_in[1];   // [3072, 1024]
    const float* b1  = (const float*)d_in[2];   // [3072]
    const float* w2  = (const float*)d_in[3];   // [1024, 1024]
    const float* b2  = (const float*)d_in[4];   // [1024]
    const int*   msk = (const int*)  d_in[5];   // causal flag
    float* out = (float*)d_out;

    const int M = BATCH * SEQ;   // 8192

    cudaFuncSetAttribute(gemm_mma<0>,
                         cudaFuncAttributeMaxDynamicSharedMemorySize, GEMM_SMEM);
    cudaFuncSetAttribute(gemm_mma<1>,
                         cudaFuncAttributeMaxDynamicSharedMemorySize, GEMM_SMEM);
    cudaFuncSetAttribute(flash_mma,
                         cudaFuncAttributeMaxDynamicSharedMemorySize, FLASH_SMEM);

    // 0) pre-round inputs to TF32 (one cheap pass)
    float* d_xr;  cudaGetSymbolAddress((void**)&d_xr,  g_xr);
    float* d_w1r; cudaGetSymbolAddress((void**)&d_w1r, g_w1r);
    float* d_w2r; cudaGetSymbolAddress((void**)&d_w2r, g_w2r);
    {
        const int nx = M * DMODEL / 4;
        round_tf32_k<<<(nx + 255) / 256, 256>>>(x, d_xr, nx);
        const int n1 = 3 * DMODEL * DMODEL / 4;
        round_tf32_k<<<(n1 + 255) / 256, 256>>>(w1, d_w1r, n1);
        const int n2 = DMODEL * DMODEL / 4;
        round_tf32_k<<<(n2 + 255) / 256, 256>>>(w2, d_w2r, n2);
    }

    // 1) QKV projection -> g_q (scaled+rounded) / g_k / g_v (rounded)
    gemm_mma<0><<<dim3(3 * DMODEL / GBN, M / GBM), 256, GEMM_SMEM>>>(
        d_xr, d_w1r, b1, nullptr, M, 3 * DMODEL, DMODEL);

    // 2) Flash attention -> g_attn (rounded)
    flash_mma<<<dim3(SEQ / QTILE, NHEADS, BATCH), 256, FLASH_SMEM>>>(msk);

    // 3) Output projection -> d_out
    gemm_mma<1><<<dim3(DMODEL / GBN, M / GBM), 256, GEMM_SMEM>>>(
        nullptr, d_w2r, b2, out, M, DMODEL, DMODEL);
}